// round 14
// baseline (speedup 1.0000x reference)
#include <cuda_runtime.h>
#include <cuda_fp16.h>
#include <cstdint>
#include <cstddef>

// ===========================================================================
// SwinBlock_tp on GB300 — fp16 mma.sync GEMMs (BM=BN=128, warp 64x32,
// 2 CTA/SM, single-barrier mainloop) + HMMA attention + warp-per-row LN.
// hidden kept fp16 to cut residual-stream DRAM traffic.
// M = 131072 rows, C = 512.
// ===========================================================================

#define MROWS 131072

// ------------------------- scratch (device globals) ------------------------
__device__ __half g_xw  [(size_t)MROWS * 512];
__device__ __half g_qkv [(size_t)MROWS * 1536];
__device__ __half g_ctx [(size_t)MROWS * 512];
__device__ __half g_hidh[(size_t)MROWS * 512];
__device__ __half g_zln [(size_t)MROWS * 512];
__device__ __half g_fc1 [(size_t)MROWS * 2048];
// transposed weights [N][K] fp16
__device__ __half g_wq[1536 * 512];
__device__ __half g_wp[512 * 512];
__device__ __half g_w1[2048 * 512];
__device__ __half g_w2[512 * 2048];

// ------------------------------ PTX helpers --------------------------------
__device__ __forceinline__ uint32_t smem_u32(const void* p) {
    uint32_t a;
    asm("{ .reg .u64 t; cvta.to.shared.u64 t, %1; cvt.u32.u64 %0, t; }" : "=r"(a) : "l"(p));
    return a;
}
__device__ __forceinline__ void cp16(uint32_t dst, const void* src) {
    asm volatile("cp.async.cg.shared.global [%0], [%1], 16;\n" :: "r"(dst), "l"(src) : "memory");
}
#define CP_COMMIT() asm volatile("cp.async.commit_group;\n" ::: "memory")
template<int N> __device__ __forceinline__ void cp_wait() {
    asm volatile("cp.async.wait_group %0;\n" :: "n"(N) : "memory");
}
__device__ __forceinline__ void ldsm4(uint32_t* r, uint32_t addr) {
    asm volatile("ldmatrix.sync.aligned.m8n8.x4.shared.b16 {%0,%1,%2,%3}, [%4];"
        : "=r"(r[0]), "=r"(r[1]), "=r"(r[2]), "=r"(r[3]) : "r"(addr));
}
__device__ __forceinline__ void ldsm4t(uint32_t* r, uint32_t addr) {
    asm volatile("ldmatrix.sync.aligned.m8n8.x4.trans.shared.b16 {%0,%1,%2,%3}, [%4];"
        : "=r"(r[0]), "=r"(r[1]), "=r"(r[2]), "=r"(r[3]) : "r"(addr));
}
__device__ __forceinline__ void mma16816(float* d, const uint32_t* a, const uint32_t* b) {
    asm volatile("mma.sync.aligned.m16n8k16.row.col.f32.f16.f16.f32 "
        "{%0,%1,%2,%3}, {%4,%5,%6,%7}, {%8,%9}, {%0,%1,%2,%3};"
        : "+f"(d[0]), "+f"(d[1]), "+f"(d[2]), "+f"(d[3])
        : "r"(a[0]), "r"(a[1]), "r"(a[2]), "r"(a[3]), "r"(b[0]), "r"(b[1]));
}

// ------------------------------ small helpers ------------------------------
__device__ __forceinline__ float gelu_exact(float x) {
    return 0.5f * x * (1.0f + erff(x * 0.70710678118654752f));
}
__device__ __forceinline__ void warp_reduce2(float& sum, float& sq) {
    #pragma unroll
    for (int o = 16; o > 0; o >>= 1) {
        sum += __shfl_xor_sync(0xffffffffu, sum, o);
        sq  += __shfl_xor_sync(0xffffffffu, sq,  o);
    }
}

// ---------------------------------------------------------------------------
// K0: fused weight transpose  W[K,N] -> Wt[N,K] fp16, all 4 weights, 1 launch
// tile ids: [0,768) wq | [768,1024) wp | [1024,2048) w1 | [2048,3072) w2
// ---------------------------------------------------------------------------
__global__ void wprep_all(const float* __restrict__ Wq, const float* __restrict__ Wp,
                          const float* __restrict__ W1, const float* __restrict__ W2,
                          __half* __restrict__ Tq, __half* __restrict__ Tp,
                          __half* __restrict__ T1, __half* __restrict__ T2) {
    __shared__ float tile[32][33];
    int id = blockIdx.x;
    const float* W; __half* T; int K, N, nb, kb;
    if (id < 768)       { W = Wq; T = Tq; K = 512;  N = 1536; int r = id;        nb = (r % 48) * 32; kb = (r / 48) * 32; }
    else if (id < 1024) { W = Wp; T = Tp; K = 512;  N = 512;  int r = id - 768;  nb = (r % 16) * 32; kb = (r / 16) * 32; }
    else if (id < 2048) { W = W1; T = T1; K = 512;  N = 2048; int r = id - 1024; nb = (r % 64) * 32; kb = (r / 64) * 32; }
    else                { W = W2; T = T2; K = 2048; N = 512;  int r = id - 2048; nb = (r % 16) * 32; kb = (r / 16) * 32; }

    int tx = threadIdx.x & 31, ty = threadIdx.x >> 5;
    #pragma unroll
    for (int i = ty; i < 32; i += 8)
        tile[i][tx] = W[(size_t)(kb + i) * N + nb + tx];
    __syncthreads();
    #pragma unroll
    for (int i = ty; i < 32; i += 8)
        T[(size_t)(nb + i) * K + kb + tx] = __float2half(tile[tx][i]);
}

// ---------------------------------------------------------------------------
// K1: LN1 + roll(-4,-4) + window partition -> fp16.  Warp-per-row.
// ---------------------------------------------------------------------------
__global__ __launch_bounds__(256) void ln_shift_warp(const float* __restrict__ x,
                                                     const float* __restrict__ g,
                                                     const float* __restrict__ b,
                                                     __half* __restrict__ out) {
    int wg = (blockIdx.x * 256 + threadIdx.x) >> 5;
    int lane = threadIdx.x & 31;

    float4 gv[4], bv[4];
    #pragma unroll
    for (int k = 0; k < 4; k++) {
        gv[k] = *(const float4*)(g + (k * 32 + lane) * 4);
        bv[k] = *(const float4*)(b + (k * 32 + lane) * 4);
    }

    #pragma unroll
    for (int rw = 0; rw < 8; rw++) {
        int r = wg * 8 + rw;
        int s = r >> 11, n = r & 2047;
        int hn = s >> 3, wn = s & 7;
        int i = n >> 8, j = (n >> 5) & 7, bb = n & 31;
        int h = ((hn << 3) + i + 4) & 63;
        int w = ((wn << 3) + j + 4) & 63;
        size_t src = ((size_t)((h << 6) + w) * 32 + bb) * 512;

        float4 v[4];
        float sum = 0.0f, sq = 0.0f;
        #pragma unroll
        for (int k = 0; k < 4; k++) {
            v[k] = *(const float4*)(x + src + (k * 32 + lane) * 4);
            sum += v[k].x + v[k].y + v[k].z + v[k].w;
            sq  += v[k].x*v[k].x + v[k].y*v[k].y + v[k].z*v[k].z + v[k].w*v[k].w;
        }
        warp_reduce2(sum, sq);
        float mu = sum * (1.0f/512.0f);
        float rstd = rsqrtf(sq * (1.0f/512.0f) - mu*mu + 1e-5f);

        size_t dst = (size_t)r * 512;
        #pragma unroll
        for (int k = 0; k < 4; k++) {
            __half2 h0 = __floats2half2_rn((v[k].x - mu)*rstd*gv[k].x + bv[k].x,
                                           (v[k].y - mu)*rstd*gv[k].y + bv[k].y);
            __half2 h1 = __floats2half2_rn((v[k].z - mu)*rstd*gv[k].z + bv[k].z,
                                           (v[k].w - mu)*rstd*gv[k].w + bv[k].w);
            uint2 u; u.x = *(uint32_t*)&h0; u.y = *(uint32_t*)&h1;
            *(uint2*)(out + dst + (k * 32 + lane) * 4) = u;
        }
    }
}

// ---------------------------------------------------------------------------
// K5b: LN2 over fp16 hidden (token domain) -> zln fp16.  Warp-per-row.
// ---------------------------------------------------------------------------
__global__ __launch_bounds__(256) void ln2_warp(const __half* __restrict__ hid,
                                                const float* __restrict__ g,
                                                const float* __restrict__ b,
                                                __half* __restrict__ zln) {
    int wg = (blockIdx.x * 256 + threadIdx.x) >> 5;
    int lane = threadIdx.x & 31;

    float4 gv[4], bv[4];
    #pragma unroll
    for (int k = 0; k < 4; k++) {
        gv[k] = *(const float4*)(g + (k * 32 + lane) * 4);
        bv[k] = *(const float4*)(b + (k * 32 + lane) * 4);
    }

    #pragma unroll
    for (int rw = 0; rw < 8; rw++) {
        int m = wg * 8 + rw;
        size_t src = (size_t)m * 512;
        float v[16];
        float sum = 0.0f, sq = 0.0f;
        #pragma unroll
        for (int k = 0; k < 4; k++) {
            uint2 u = *(const uint2*)(hid + src + (k * 32 + lane) * 4);
            float2 f0 = __half22float2(*(__half2*)&u.x);
            float2 f1 = __half22float2(*(__half2*)&u.y);
            v[k*4+0] = f0.x; v[k*4+1] = f0.y; v[k*4+2] = f1.x; v[k*4+3] = f1.y;
            sum += f0.x + f0.y + f1.x + f1.y;
            sq  += f0.x*f0.x + f0.y*f0.y + f1.x*f1.x + f1.y*f1.y;
        }
        warp_reduce2(sum, sq);
        float mu = sum * (1.0f/512.0f);
        float rstd = rsqrtf(sq * (1.0f/512.0f) - mu*mu + 1e-5f);

        #pragma unroll
        for (int k = 0; k < 4; k++) {
            __half2 h0 = __floats2half2_rn((v[k*4+0] - mu)*rstd*gv[k].x + bv[k].x,
                                           (v[k*4+1] - mu)*rstd*gv[k].y + bv[k].y);
            __half2 h1 = __floats2half2_rn((v[k*4+2] - mu)*rstd*gv[k].z + bv[k].z,
                                           (v[k*4+3] - mu)*rstd*gv[k].w + bv[k].w);
            uint2 u; u.x = *(uint32_t*)&h0; u.y = *(uint32_t*)&h1;
            *(uint2*)(zln + src + (k * 32 + lane) * 4) = u;
        }
    }
}

// ---------------------------------------------------------------------------
// K3: HMMA attention. CTA = (n, head-pair): 256 threads, 8 warps.
// ---------------------------------------------------------------------------
__device__ __forceinline__ int region_id(int c) { return c < 56 ? 0 : (c < 60 ? 1 : 2); }

#define ATT_PITCH 80
#define ATT_TILE  (64 * ATT_PITCH)

__global__ __launch_bounds__(256) void attn_kernel(const __half* __restrict__ qkv,
                                                   __half* __restrict__ ctx) {
    __shared__ __half sAll[2][3][64 * 40];
    __shared__ int val[64];

    const int n = blockIdx.x, t = threadIdx.x;
    const int lane = t & 31, wid = t >> 5;
    const int hg = wid >> 2, w = wid & 3;
    const int h = blockIdx.y * 2 + hg;
    const uint32_t sbase = smem_u32(&sAll[0][0][0]);

    #pragma unroll
    for (int i = 0; i < 6; i++) {
        int f = t + i * 256;
        int hg2  = f / 768;
        int rem  = f - hg2 * 768;
        int part = rem >> 8;
        int rr   = rem & 255;
        int row  = rr >> 2, seg = rr & 3;
        const __half* src = qkv + (size_t)(row * 2048 + n) * 1536
                          + (blockIdx.y * 2 + hg2) * 96 + part * 32 + seg * 8;
        cp16(sbase + (hg2 * 3 + part) * ATT_TILE + row * ATT_PITCH + seg * 16, src);
    }
    CP_COMMIT();
    if (t < 64) {
        int mw = n & 63;
        int hh = ((mw >> 3) << 3) + (t >> 3);
        int ww = ((mw & 7) << 3) + (t & 7);
        val[t] = region_id(hh) * 3 + region_id(ww);
    }
    cp_wait<0>();
    __syncthreads();

    const uint32_t qb = sbase + (hg * 3 + 0) * ATT_TILE;
    const uint32_t kb = sbase + (hg * 3 + 1) * ATT_TILE;
    const uint32_t vb = sbase + (hg * 3 + 2) * ATT_TILE;

    float d[8][4];
    #pragma unroll
    for (int nt = 0; nt < 8; nt++)
        #pragma unroll
        for (int j = 0; j < 4; j++) d[nt][j] = 0.0f;

    #pragma unroll
    for (int ks = 0; ks < 2; ks++) {
        uint32_t af[4];
        ldsm4(af, qb + (w * 16 + (lane & 15)) * ATT_PITCH + (ks * 2 + (lane >> 4)) * 16);
        uint32_t bf[8][2];
        int g = lane >> 3;
        #pragma unroll
        for (int np = 0; np < 4; np++) {
            uint32_t tmp[4];
            ldsm4(tmp, kb + (np * 16 + (g >> 1) * 8 + (lane & 7)) * ATT_PITCH
                          + (ks * 2 + (g & 1)) * 16);
            bf[np*2][0]   = tmp[0]; bf[np*2][1]   = tmp[1];
            bf[np*2+1][0] = tmp[2]; bf[np*2+1][1] = tmp[3];
        }
        #pragma unroll
        for (int nt = 0; nt < 8; nt++) mma16816(d[nt], af, bf[nt]);
    }

    const int r0 = lane >> 2;
    const int c0 = 2 * (lane & 3);
    const int vs0 = val[w * 16 + r0];
    const int vs1 = val[w * 16 + r0 + 8];
    const float SCALE = 0.17677669529663687f;

    float mx0 = -1e30f, mx1 = -1e30f;
    #pragma unroll
    for (int nt = 0; nt < 8; nt++) {
        int vc0 = val[nt * 8 + c0], vc1 = val[nt * 8 + c0 + 1];
        d[nt][0] = (vc0 != vs0) ? -10000.0f : d[nt][0] * SCALE;
        d[nt][1] = (vc1 != vs0) ? -10000.0f : d[nt][1] * SCALE;
        d[nt][2] = (vc0 != vs1) ? -10000.0f : d[nt][2] * SCALE;
        d[nt][3] = (vc1 != vs1) ? -10000.0f : d[nt][3] * SCALE;
        mx0 = fmaxf(mx0, fmaxf(d[nt][0], d[nt][1]));
        mx1 = fmaxf(mx1, fmaxf(d[nt][2], d[nt][3]));
    }
    mx0 = fmaxf(mx0, __shfl_xor_sync(0xffffffffu, mx0, 1));
    mx0 = fmaxf(mx0, __shfl_xor_sync(0xffffffffu, mx0, 2));
    mx1 = fmaxf(mx1, __shfl_xor_sync(0xffffffffu, mx1, 1));
    mx1 = fmaxf(mx1, __shfl_xor_sync(0xffffffffu, mx1, 2));

    float s0 = 0.0f, s1 = 0.0f;
    #pragma unroll
    for (int nt = 0; nt < 8; nt++) {
        d[nt][0] = __expf(d[nt][0] - mx0);
        d[nt][1] = __expf(d[nt][1] - mx0);
        d[nt][2] = __expf(d[nt][2] - mx1);
        d[nt][3] = __expf(d[nt][3] - mx1);
        s0 += d[nt][0] + d[nt][1];
        s1 += d[nt][2] + d[nt][3];
    }
    s0 += __shfl_xor_sync(0xffffffffu, s0, 1);
    s0 += __shfl_xor_sync(0xffffffffu, s0, 2);
    s1 += __shfl_xor_sync(0xffffffffu, s1, 1);
    s1 += __shfl_xor_sync(0xffffffffu, s1, 2);
    const float inv0 = 1.0f / s0, inv1 = 1.0f / s1;

    uint32_t pf[4][4];
    #pragma unroll
    for (int kt = 0; kt < 4; kt++) {
        __half2 a0 = __floats2half2_rn(d[2*kt][0]   * inv0, d[2*kt][1]   * inv0);
        __half2 a1 = __floats2half2_rn(d[2*kt][2]   * inv1, d[2*kt][3]   * inv1);
        __half2 a2 = __floats2half2_rn(d[2*kt+1][0] * inv0, d[2*kt+1][1] * inv0);
        __half2 a3 = __floats2half2_rn(d[2*kt+1][2] * inv1, d[2*kt+1][3] * inv1);
        pf[kt][0] = *(uint32_t*)&a0; pf[kt][1] = *(uint32_t*)&a1;
        pf[kt][2] = *(uint32_t*)&a2; pf[kt][3] = *(uint32_t*)&a3;
    }

    float o[4][4];
    #pragma unroll
    for (int dt = 0; dt < 4; dt++)
        #pragma unroll
        for (int j = 0; j < 4; j++) o[dt][j] = 0.0f;

    {
        int g = lane >> 3;
        #pragma unroll
        for (int kt = 0; kt < 4; kt++) {
            uint32_t bv[4][2];
            #pragma unroll
            for (int dp = 0; dp < 2; dp++) {
                uint32_t tmp[4];
                ldsm4t(tmp, vb + (kt * 16 + (g & 1) * 8 + (lane & 7)) * ATT_PITCH
                               + dp * 32 + (g >> 1) * 16);
                bv[dp*2][0]   = tmp[0]; bv[dp*2][1]   = tmp[1];
                bv[dp*2+1][0] = tmp[2]; bv[dp*2+1][1] = tmp[3];
            }
            #pragma unroll
            for (int dt = 0; dt < 4; dt++) mma16816(o[dt], pf[kt], bv[dt]);
        }
    }

    const int srow0 = w * 16 + r0;
    const size_t base0 = (size_t)(srow0 * 2048 + n) * 512 + h * 32;
    const size_t base1 = (size_t)((srow0 + 8) * 2048 + n) * 512 + h * 32;
    #pragma unroll
    for (int dt = 0; dt < 4; dt++) {
        int c = dt * 8 + c0;
        __half2 h0 = __floats2half2_rn(o[dt][0], o[dt][1]);
        __half2 h1 = __floats2half2_rn(o[dt][2], o[dt][3]);
        *(__half2*)(ctx + base0 + c) = h0;
        *(__half2*)(ctx + base1 + c) = h1;
    }
}

// ---------------------------------------------------------------------------
// hgemm: out[M,Ntot] = A[M,K](fp16) @ Wt[Ntot,K](fp16)^T + bias (+epilogue)
// BM=BN=128, BK=32, 8 warps (2m x 4n), warp tile 64x32, mma.m16n8k16.
// Single barrier per K-iter; B frags via paired ldsm4.
// EPI: 0 fp16 out; 2 gelu -> fp16;
//      3 final: out32 = acc + bias + rh(zln) + rh2(hidden fp16)
//      4 hidden-writer: outh[perm(row)] = fp16(acc + bias + rh[row](xw)
//                                              + r32[perm(row)](shortcut))
// ---------------------------------------------------------------------------
#define APITCH   80
#define TILE_B   (128 * APITCH)
#define STAGE_B  (2 * TILE_B)
#define NSTAGE   4
#define SMEM_T   (NSTAGE * STAGE_B)

__device__ __forceinline__ void load_stage(uint32_t sm, int stage,
                                           const __half* A, const __half* Bt,
                                           int K, int m0, int n0, int kk, int t) {
    uint32_t ab = sm + stage * STAGE_B;
    uint32_t bb = ab + TILE_B;
    #pragma unroll
    for (int i = 0; i < 2; i++) {
        int f = t + i * 256;
        int row = f >> 2, seg = f & 3;
        cp16(ab + row * APITCH + seg * 16, A + (size_t)(m0 + row) * K + kk + seg * 8);
    }
    #pragma unroll
    for (int i = 0; i < 2; i++) {
        int f = t + i * 256;
        int row = f >> 2, seg = f & 3;
        cp16(bb + row * APITCH + seg * 16, Bt + (size_t)(n0 + row) * K + kk + seg * 8);
    }
    CP_COMMIT();
}

__device__ __forceinline__ int perm_row(int R) {
    int s = R >> 11, n = R & 2047;
    int hn = s >> 3, wn = s & 7;
    int i = n >> 8, j = (n >> 5) & 7, b = n & 31;
    int h = ((hn << 3) + i + 4) & 63;
    int w = ((wn << 3) + j + 4) & 63;
    return ((h << 6) + w) * 32 + b;
}

template<int EPI>
__global__ void __launch_bounds__(256) hgemm(
    const __half* __restrict__ A, const __half* __restrict__ Bt,
    const float* __restrict__ bias,
    const float* __restrict__ r32,
    const __half* __restrict__ rh, const __half* __restrict__ rh2,
    float* __restrict__ out32, __half* __restrict__ outh,
    int Ntot, int K)
{
    extern __shared__ char smem[];
    uint32_t sm = smem_u32(smem);
    int t = threadIdx.x;
    int lane = t & 31, wid = t >> 5;
    int wm = wid & 1, wn = wid >> 1;
    int m0 = blockIdx.y * 128;
    int n0 = blockIdx.x * 128;
    int NI = K / 32;

    float d[4][4][4];
    #pragma unroll
    for (int a = 0; a < 4; a++)
        #pragma unroll
        for (int b = 0; b < 4; b++)
            #pragma unroll
            for (int c = 0; c < 4; c++) d[a][b][c] = 0.0f;

    load_stage(sm, 0, A, Bt, K, m0, n0, 0, t);
    load_stage(sm, 1, A, Bt, K, m0, n0, 32, t);
    load_stage(sm, 2, A, Bt, K, m0, n0, 64, t);

    for (int it = 0; it < NI; it++) {
        cp_wait<2>();
        __syncthreads();
        // All warps are past iter it-1's fragment reads of stage (it+3)&3,
        // so it's safe to refill it now (cutlass multistage pattern).
        if (it + 3 < NI) load_stage(sm, (it + 3) & 3, A, Bt, K, m0, n0, (it + 3) * 32, t);
        else CP_COMMIT();

        uint32_t ab = sm + (it & 3) * STAGE_B;
        uint32_t bb = ab + TILE_B;
        #pragma unroll
        for (int ks = 0; ks < 2; ks++) {
            uint32_t af[4][4], bf[4][2];
            #pragma unroll
            for (int mt = 0; mt < 4; mt++) {
                int row = wm * 64 + mt * 16 + (lane & 15);
                int seg = ks * 2 + (lane >> 4);
                ldsm4(af[mt], ab + row * APITCH + seg * 16);
            }
            {
                int g = lane >> 3;
                #pragma unroll
                for (int np = 0; np < 2; np++) {
                    uint32_t tmp[4];
                    int row = wn * 32 + np * 16 + (g >> 1) * 8 + (lane & 7);
                    int seg = ks * 2 + (g & 1);
                    ldsm4(tmp, bb + row * APITCH + seg * 16);
                    bf[np*2][0]   = tmp[0]; bf[np*2][1]   = tmp[1];
                    bf[np*2+1][0] = tmp[2]; bf[np*2+1][1] = tmp[3];
                }
            }
            #pragma unroll
            for (int mt = 0; mt < 4; mt++)
                #pragma unroll
                for (int nt = 0; nt < 4; nt++)
                    mma16816(d[mt][nt], af[mt], bf[nt]);
        }
        // no end-of-iter barrier: next iter's top barrier provides the fence
    }

    // ---------------- epilogue ----------------
    #pragma unroll
    for (int mt = 0; mt < 4; mt++) {
        int r0 = m0 + wm * 64 + mt * 16 + (lane >> 2);
        #pragma unroll
        for (int hf = 0; hf < 2; hf++) {
            int R = r0 + hf * 8;
            size_t gr = (size_t)R * Ntot;
            size_t pr = (EPI == 4) ? (size_t)perm_row(R) * Ntot : 0;
            #pragma unroll
            for (int nt = 0; nt < 4; nt++) {
                int c = n0 + wn * 32 + nt * 8 + (lane & 3) * 2;
                float2 bv = *(const float2*)(bias + c);
                float x = d[mt][nt][hf * 2 + 0] + bv.x;
                float y = d[mt][nt][hf * 2 + 1] + bv.y;
                if (EPI == 0) {
                    *(__half2*)(outh + gr + c) = __floats2half2_rn(x, y);
                } else if (EPI == 2) {
                    *(__half2*)(outh + gr + c) = __floats2half2_rn(gelu_exact(x), gelu_exact(y));
                } else if (EPI == 3) {
                    float2 rv = __half22float2(*(const __half2*)(rh + gr + c));
                    float2 hv = __half22float2(*(const __half2*)(rh2 + gr + c));
                    float2 o = {x + rv.x + hv.x, y + rv.y + hv.y};
                    *(float2*)(out32 + gr + c) = o;
                } else {  // EPI == 4
                    float2 rv = __half22float2(*(const __half2*)(rh + gr + c));
                    float2 sv = *(const float2*)(r32 + pr + c);
                    *(__half2*)(outh + pr + c) =
                        __floats2half2_rn(x + rv.x + sv.x, y + rv.y + sv.y);
                }
            }
        }
    }
}

// ---------------------------------------------------------------------------
// Launch
// ---------------------------------------------------------------------------
extern "C" void kernel_launch(void* const* d_in, const int* in_sizes, int n_in,
                              void* d_out, int out_size) {
    const float* hs    = (const float*)d_in[0];
    const float* ln1g  = (const float*)d_in[1];
    const float* ln1b  = (const float*)d_in[2];
    const float* wqkv  = (const float*)d_in[3];
    const float* bqkv  = (const float*)d_in[4];
    const float* wproj = (const float*)d_in[5];
    const float* bproj = (const float*)d_in[6];
    const float* ln2g  = (const float*)d_in[7];
    const float* ln2b  = (const float*)d_in[8];
    const float* wfc1  = (const float*)d_in[9];
    const float* bfc1  = (const float*)d_in[10];
    const float* wfc2  = (const float*)d_in[11];
    const float* bfc2  = (const float*)d_in[12];
    float* out = (float*)d_out;

    __half *p_xw, *p_qkv, *p_ctx, *p_hidh, *p_zln, *p_fc1, *p_wq, *p_wp, *p_w1, *p_w2;
    cudaGetSymbolAddress((void**)&p_xw,   g_xw);
    cudaGetSymbolAddress((void**)&p_qkv,  g_qkv);
    cudaGetSymbolAddress((void**)&p_ctx,  g_ctx);
    cudaGetSymbolAddress((void**)&p_hidh, g_hidh);
    cudaGetSymbolAddress((void**)&p_zln,  g_zln);
    cudaGetSymbolAddress((void**)&p_fc1,  g_fc1);
    cudaGetSymbolAddress((void**)&p_wq,   g_wq);
    cudaGetSymbolAddress((void**)&p_wp,   g_wp);
    cudaGetSymbolAddress((void**)&p_w1,   g_w1);
    cudaGetSymbolAddress((void**)&p_w2,   g_w2);

    cudaFuncSetAttribute(hgemm<0>, cudaFuncAttributeMaxDynamicSharedMemorySize, SMEM_T);
    cudaFuncSetAttribute(hgemm<2>, cudaFuncAttributeMaxDynamicSharedMemorySize, SMEM_T);
    cudaFuncSetAttribute(hgemm<3>, cudaFuncAttributeMaxDynamicSharedMemorySize, SMEM_T);
    cudaFuncSetAttribute(hgemm<4>, cudaFuncAttributeMaxDynamicSharedMemorySize, SMEM_T);

    // fused weight transpose -> fp16 [N][K]
    wprep_all<<<3072, 256>>>(wqkv, wproj, wfc1, wfc2, p_wq, p_wp, p_w1, p_w2);

    // LN1 + shift + partition (warp-per-row)
    ln_shift_warp<<<2048, 256>>>(hs, ln1g, ln1b, p_xw);

    // qkv = xw @ Wqkv + b           -> fp16
    hgemm<0><<<dim3(12, 1024), 256, SMEM_T>>>(p_xw, p_wq, bqkv,
        nullptr, nullptr, nullptr, nullptr, p_qkv, 1536, 512);

    // attention (HMMA)
    attn_kernel<<<dim3(2048, 8), 256>>>(p_qkv, p_ctx);

    // hidden[perm] = fp16(ctx @ Wproj + b + xw + shortcut[perm])
    hgemm<4><<<dim3(4, 1024), 256, SMEM_T>>>(p_ctx, p_wp, bproj,
        hs, p_xw, nullptr, nullptr, p_hidh, 512, 512);

    // zln = LN2(hidden)  (warp-per-row, fp16 in)
    ln2_warp<<<2048, 256>>>(p_hidh, ln2g, ln2b, p_zln);

    // fc1 = gelu(zln @ Wfc1 + b)    -> fp16
    hgemm<2><<<dim3(16, 1024), 256, SMEM_T>>>(p_zln, p_w1, bfc1,
        nullptr, nullptr, nullptr, nullptr, p_fc1, 2048, 512);

    // out = fc1 @ Wfc2 + b + zln + hidden
    hgemm<3><<<dim3(4, 1024), 256, SMEM_T>>>(p_fc1, p_w2, bfc2,
        nullptr, p_zln, p_hidh, out, nullptr, 512, 2048);
}

// round 15
// speedup vs baseline: 1.0215x; 1.0215x over previous
#include <cuda_runtime.h>
#include <cuda_fp16.h>
#include <cstdint>
#include <cstddef>

// ===========================================================================
// SwinBlock_tp on GB300 — fp16 mma.sync GEMMs (BM=BN=128, warp 64x32,
// 2 CTA/SM, single-barrier mainloop) + HMMA attention + warp-per-row LN.
// Round-13 config (fp32 hidden) + fused single-launch weight prep.
// M = 131072 rows, C = 512.
// ===========================================================================

#define MROWS 131072

// ------------------------- scratch (device globals) ------------------------
__device__ __half g_xw [(size_t)MROWS * 512];
__device__ __half g_qkv[(size_t)MROWS * 1536];
__device__ __half g_ctx[(size_t)MROWS * 512];
__device__ float  g_hid [(size_t)MROWS * 512];
__device__ __half g_zln[(size_t)MROWS * 512];
__device__ __half g_fc1[(size_t)MROWS * 2048];
// transposed weights [N][K] fp16
__device__ __half g_wq[1536 * 512];
__device__ __half g_wp[512 * 512];
__device__ __half g_w1[2048 * 512];
__device__ __half g_w2[512 * 2048];

// ------------------------------ PTX helpers --------------------------------
__device__ __forceinline__ uint32_t smem_u32(const void* p) {
    uint32_t a;
    asm("{ .reg .u64 t; cvta.to.shared.u64 t, %1; cvt.u32.u64 %0, t; }" : "=r"(a) : "l"(p));
    return a;
}
__device__ __forceinline__ void cp16(uint32_t dst, const void* src) {
    asm volatile("cp.async.cg.shared.global [%0], [%1], 16;\n" :: "r"(dst), "l"(src) : "memory");
}
#define CP_COMMIT() asm volatile("cp.async.commit_group;\n" ::: "memory")
template<int N> __device__ __forceinline__ void cp_wait() {
    asm volatile("cp.async.wait_group %0;\n" :: "n"(N) : "memory");
}
__device__ __forceinline__ void ldsm4(uint32_t* r, uint32_t addr) {
    asm volatile("ldmatrix.sync.aligned.m8n8.x4.shared.b16 {%0,%1,%2,%3}, [%4];"
        : "=r"(r[0]), "=r"(r[1]), "=r"(r[2]), "=r"(r[3]) : "r"(addr));
}
__device__ __forceinline__ void ldsm4t(uint32_t* r, uint32_t addr) {
    asm volatile("ldmatrix.sync.aligned.m8n8.x4.trans.shared.b16 {%0,%1,%2,%3}, [%4];"
        : "=r"(r[0]), "=r"(r[1]), "=r"(r[2]), "=r"(r[3]) : "r"(addr));
}
__device__ __forceinline__ void mma16816(float* d, const uint32_t* a, const uint32_t* b) {
    asm volatile("mma.sync.aligned.m16n8k16.row.col.f32.f16.f16.f32 "
        "{%0,%1,%2,%3}, {%4,%5,%6,%7}, {%8,%9}, {%0,%1,%2,%3};"
        : "+f"(d[0]), "+f"(d[1]), "+f"(d[2]), "+f"(d[3])
        : "r"(a[0]), "r"(a[1]), "r"(a[2]), "r"(a[3]), "r"(b[0]), "r"(b[1]));
}

// ------------------------------ small helpers ------------------------------
__device__ __forceinline__ float gelu_exact(float x) {
    return 0.5f * x * (1.0f + erff(x * 0.70710678118654752f));
}
__device__ __forceinline__ void warp_reduce2(float& sum, float& sq) {
    #pragma unroll
    for (int o = 16; o > 0; o >>= 1) {
        sum += __shfl_xor_sync(0xffffffffu, sum, o);
        sq  += __shfl_xor_sync(0xffffffffu, sq,  o);
    }
}

// ---------------------------------------------------------------------------
// K0: fused weight transpose  W[K,N] -> Wt[N,K] fp16, all 4 weights, 1 launch
// tile ids: [0,768) wq | [768,1024) wp | [1024,2048) w1 | [2048,3072) w2
// ---------------------------------------------------------------------------
__global__ void wprep_all(const float* __restrict__ Wq, const float* __restrict__ Wp,
                          const float* __restrict__ W1, const float* __restrict__ W2,
                          __half* __restrict__ Tq, __half* __restrict__ Tp,
                          __half* __restrict__ T1, __half* __restrict__ T2) {
    __shared__ float tile[32][33];
    int id = blockIdx.x;
    const float* W; __half* T; int K, N, nb, kb;
    if (id < 768)       { W = Wq; T = Tq; K = 512;  N = 1536; int r = id;        nb = (r % 48) * 32; kb = (r / 48) * 32; }
    else if (id < 1024) { W = Wp; T = Tp; K = 512;  N = 512;  int r = id - 768;  nb = (r % 16) * 32; kb = (r / 16) * 32; }
    else if (id < 2048) { W = W1; T = T1; K = 512;  N = 2048; int r = id - 1024; nb = (r % 64) * 32; kb = (r / 64) * 32; }
    else                { W = W2; T = T2; K = 2048; N = 512;  int r = id - 2048; nb = (r % 16) * 32; kb = (r / 16) * 32; }

    int tx = threadIdx.x & 31, ty = threadIdx.x >> 5;
    #pragma unroll
    for (int i = ty; i < 32; i += 8)
        tile[i][tx] = W[(size_t)(kb + i) * N + nb + tx];
    __syncthreads();
    #pragma unroll
    for (int i = ty; i < 32; i += 8)
        T[(size_t)(nb + i) * K + kb + tx] = __float2half(tile[tx][i]);
}

// ---------------------------------------------------------------------------
// K1: LN1 + roll(-4,-4) + window partition -> fp16.  Warp-per-row.
// ---------------------------------------------------------------------------
__global__ __launch_bounds__(256) void ln_shift_warp(const float* __restrict__ x,
                                                     const float* __restrict__ g,
                                                     const float* __restrict__ b,
                                                     __half* __restrict__ out) {
    int wg = (blockIdx.x * 256 + threadIdx.x) >> 5;
    int lane = threadIdx.x & 31;

    float4 gv[4], bv[4];
    #pragma unroll
    for (int k = 0; k < 4; k++) {
        gv[k] = *(const float4*)(g + (k * 32 + lane) * 4);
        bv[k] = *(const float4*)(b + (k * 32 + lane) * 4);
    }

    #pragma unroll
    for (int rw = 0; rw < 8; rw++) {
        int r = wg * 8 + rw;
        int s = r >> 11, n = r & 2047;
        int hn = s >> 3, wn = s & 7;
        int i = n >> 8, j = (n >> 5) & 7, bb = n & 31;
        int h = ((hn << 3) + i + 4) & 63;
        int w = ((wn << 3) + j + 4) & 63;
        size_t src = ((size_t)((h << 6) + w) * 32 + bb) * 512;

        float4 v[4];
        float sum = 0.0f, sq = 0.0f;
        #pragma unroll
        for (int k = 0; k < 4; k++) {
            v[k] = *(const float4*)(x + src + (k * 32 + lane) * 4);
            sum += v[k].x + v[k].y + v[k].z + v[k].w;
            sq  += v[k].x*v[k].x + v[k].y*v[k].y + v[k].z*v[k].z + v[k].w*v[k].w;
        }
        warp_reduce2(sum, sq);
        float mu = sum * (1.0f/512.0f);
        float rstd = rsqrtf(sq * (1.0f/512.0f) - mu*mu + 1e-5f);

        size_t dst = (size_t)r * 512;
        #pragma unroll
        for (int k = 0; k < 4; k++) {
            __half2 h0 = __floats2half2_rn((v[k].x - mu)*rstd*gv[k].x + bv[k].x,
                                           (v[k].y - mu)*rstd*gv[k].y + bv[k].y);
            __half2 h1 = __floats2half2_rn((v[k].z - mu)*rstd*gv[k].z + bv[k].z,
                                           (v[k].w - mu)*rstd*gv[k].w + bv[k].w);
            uint2 u; u.x = *(uint32_t*)&h0; u.y = *(uint32_t*)&h1;
            *(uint2*)(out + dst + (k * 32 + lane) * 4) = u;
        }
    }
}

// ---------------------------------------------------------------------------
// K5b: LN2 over fp32 hidden (token domain) -> zln fp16.  Warp-per-row.
// ---------------------------------------------------------------------------
__global__ __launch_bounds__(256) void ln2_warp(const float* __restrict__ hid,
                                                const float* __restrict__ g,
                                                const float* __restrict__ b,
                                                __half* __restrict__ zln) {
    int wg = (blockIdx.x * 256 + threadIdx.x) >> 5;
    int lane = threadIdx.x & 31;

    float4 gv[4], bv[4];
    #pragma unroll
    for (int k = 0; k < 4; k++) {
        gv[k] = *(const float4*)(g + (k * 32 + lane) * 4);
        bv[k] = *(const float4*)(b + (k * 32 + lane) * 4);
    }

    #pragma unroll
    for (int rw = 0; rw < 8; rw++) {
        int m = wg * 8 + rw;
        size_t src = (size_t)m * 512;
        float4 v[4];
        float sum = 0.0f, sq = 0.0f;
        #pragma unroll
        for (int k = 0; k < 4; k++) {
            v[k] = *(const float4*)(hid + src + (k * 32 + lane) * 4);
            sum += v[k].x + v[k].y + v[k].z + v[k].w;
            sq  += v[k].x*v[k].x + v[k].y*v[k].y + v[k].z*v[k].z + v[k].w*v[k].w;
        }
        warp_reduce2(sum, sq);
        float mu = sum * (1.0f/512.0f);
        float rstd = rsqrtf(sq * (1.0f/512.0f) - mu*mu + 1e-5f);

        #pragma unroll
        for (int k = 0; k < 4; k++) {
            __half2 h0 = __floats2half2_rn((v[k].x - mu)*rstd*gv[k].x + bv[k].x,
                                           (v[k].y - mu)*rstd*gv[k].y + bv[k].y);
            __half2 h1 = __floats2half2_rn((v[k].z - mu)*rstd*gv[k].z + bv[k].z,
                                           (v[k].w - mu)*rstd*gv[k].w + bv[k].w);
            uint2 u; u.x = *(uint32_t*)&h0; u.y = *(uint32_t*)&h1;
            *(uint2*)(zln + src + (k * 32 + lane) * 4) = u;
        }
    }
}

// ---------------------------------------------------------------------------
// K3: HMMA attention. CTA = (n, head-pair): 256 threads, 8 warps.
// ---------------------------------------------------------------------------
__device__ __forceinline__ int region_id(int c) { return c < 56 ? 0 : (c < 60 ? 1 : 2); }

#define ATT_PITCH 80
#define ATT_TILE  (64 * ATT_PITCH)

__global__ __launch_bounds__(256) void attn_kernel(const __half* __restrict__ qkv,
                                                   __half* __restrict__ ctx) {
    __shared__ __half sAll[2][3][64 * 40];
    __shared__ int val[64];

    const int n = blockIdx.x, t = threadIdx.x;
    const int lane = t & 31, wid = t >> 5;
    const int hg = wid >> 2, w = wid & 3;
    const int h = blockIdx.y * 2 + hg;
    const uint32_t sbase = smem_u32(&sAll[0][0][0]);

    #pragma unroll
    for (int i = 0; i < 6; i++) {
        int f = t + i * 256;
        int hg2  = f / 768;
        int rem  = f - hg2 * 768;
        int part = rem >> 8;
        int rr   = rem & 255;
        int row  = rr >> 2, seg = rr & 3;
        const __half* src = qkv + (size_t)(row * 2048 + n) * 1536
                          + (blockIdx.y * 2 + hg2) * 96 + part * 32 + seg * 8;
        cp16(sbase + (hg2 * 3 + part) * ATT_TILE + row * ATT_PITCH + seg * 16, src);
    }
    CP_COMMIT();
    if (t < 64) {
        int mw = n & 63;
        int hh = ((mw >> 3) << 3) + (t >> 3);
        int ww = ((mw & 7) << 3) + (t & 7);
        val[t] = region_id(hh) * 3 + region_id(ww);
    }
    cp_wait<0>();
    __syncthreads();

    const uint32_t qb = sbase + (hg * 3 + 0) * ATT_TILE;
    const uint32_t kb = sbase + (hg * 3 + 1) * ATT_TILE;
    const uint32_t vb = sbase + (hg * 3 + 2) * ATT_TILE;

    float d[8][4];
    #pragma unroll
    for (int nt = 0; nt < 8; nt++)
        #pragma unroll
        for (int j = 0; j < 4; j++) d[nt][j] = 0.0f;

    #pragma unroll
    for (int ks = 0; ks < 2; ks++) {
        uint32_t af[4];
        ldsm4(af, qb + (w * 16 + (lane & 15)) * ATT_PITCH + (ks * 2 + (lane >> 4)) * 16);
        uint32_t bf[8][2];
        int g = lane >> 3;
        #pragma unroll
        for (int np = 0; np < 4; np++) {
            uint32_t tmp[4];
            ldsm4(tmp, kb + (np * 16 + (g >> 1) * 8 + (lane & 7)) * ATT_PITCH
                          + (ks * 2 + (g & 1)) * 16);
            bf[np*2][0]   = tmp[0]; bf[np*2][1]   = tmp[1];
            bf[np*2+1][0] = tmp[2]; bf[np*2+1][1] = tmp[3];
        }
        #pragma unroll
        for (int nt = 0; nt < 8; nt++) mma16816(d[nt], af, bf[nt]);
    }

    const int r0 = lane >> 2;
    const int c0 = 2 * (lane & 3);
    const int vs0 = val[w * 16 + r0];
    const int vs1 = val[w * 16 + r0 + 8];
    const float SCALE = 0.17677669529663687f;

    float mx0 = -1e30f, mx1 = -1e30f;
    #pragma unroll
    for (int nt = 0; nt < 8; nt++) {
        int vc0 = val[nt * 8 + c0], vc1 = val[nt * 8 + c0 + 1];
        d[nt][0] = (vc0 != vs0) ? -10000.0f : d[nt][0] * SCALE;
        d[nt][1] = (vc1 != vs0) ? -10000.0f : d[nt][1] * SCALE;
        d[nt][2] = (vc0 != vs1) ? -10000.0f : d[nt][2] * SCALE;
        d[nt][3] = (vc1 != vs1) ? -10000.0f : d[nt][3] * SCALE;
        mx0 = fmaxf(mx0, fmaxf(d[nt][0], d[nt][1]));
        mx1 = fmaxf(mx1, fmaxf(d[nt][2], d[nt][3]));
    }
    mx0 = fmaxf(mx0, __shfl_xor_sync(0xffffffffu, mx0, 1));
    mx0 = fmaxf(mx0, __shfl_xor_sync(0xffffffffu, mx0, 2));
    mx1 = fmaxf(mx1, __shfl_xor_sync(0xffffffffu, mx1, 1));
    mx1 = fmaxf(mx1, __shfl_xor_sync(0xffffffffu, mx1, 2));

    float s0 = 0.0f, s1 = 0.0f;
    #pragma unroll
    for (int nt = 0; nt < 8; nt++) {
        d[nt][0] = __expf(d[nt][0] - mx0);
        d[nt][1] = __expf(d[nt][1] - mx0);
        d[nt][2] = __expf(d[nt][2] - mx1);
        d[nt][3] = __expf(d[nt][3] - mx1);
        s0 += d[nt][0] + d[nt][1];
        s1 += d[nt][2] + d[nt][3];
    }
    s0 += __shfl_xor_sync(0xffffffffu, s0, 1);
    s0 += __shfl_xor_sync(0xffffffffu, s0, 2);
    s1 += __shfl_xor_sync(0xffffffffu, s1, 1);
    s1 += __shfl_xor_sync(0xffffffffu, s1, 2);
    const float inv0 = 1.0f / s0, inv1 = 1.0f / s1;

    uint32_t pf[4][4];
    #pragma unroll
    for (int kt = 0; kt < 4; kt++) {
        __half2 a0 = __floats2half2_rn(d[2*kt][0]   * inv0, d[2*kt][1]   * inv0);
        __half2 a1 = __floats2half2_rn(d[2*kt][2]   * inv1, d[2*kt][3]   * inv1);
        __half2 a2 = __floats2half2_rn(d[2*kt+1][0] * inv0, d[2*kt+1][1] * inv0);
        __half2 a3 = __floats2half2_rn(d[2*kt+1][2] * inv1, d[2*kt+1][3] * inv1);
        pf[kt][0] = *(uint32_t*)&a0; pf[kt][1] = *(uint32_t*)&a1;
        pf[kt][2] = *(uint32_t*)&a2; pf[kt][3] = *(uint32_t*)&a3;
    }

    float o[4][4];
    #pragma unroll
    for (int dt = 0; dt < 4; dt++)
        #pragma unroll
        for (int j = 0; j < 4; j++) o[dt][j] = 0.0f;

    {
        int g = lane >> 3;
        #pragma unroll
        for (int kt = 0; kt < 4; kt++) {
            uint32_t bv[4][2];
            #pragma unroll
            for (int dp = 0; dp < 2; dp++) {
                uint32_t tmp[4];
                ldsm4t(tmp, vb + (kt * 16 + (g & 1) * 8 + (lane & 7)) * ATT_PITCH
                               + dp * 32 + (g >> 1) * 16);
                bv[dp*2][0]   = tmp[0]; bv[dp*2][1]   = tmp[1];
                bv[dp*2+1][0] = tmp[2]; bv[dp*2+1][1] = tmp[3];
            }
            #pragma unroll
            for (int dt = 0; dt < 4; dt++) mma16816(o[dt], pf[kt], bv[dt]);
        }
    }

    const int srow0 = w * 16 + r0;
    const size_t base0 = (size_t)(srow0 * 2048 + n) * 512 + h * 32;
    const size_t base1 = (size_t)((srow0 + 8) * 2048 + n) * 512 + h * 32;
    #pragma unroll
    for (int dt = 0; dt < 4; dt++) {
        int c = dt * 8 + c0;
        __half2 h0 = __floats2half2_rn(o[dt][0], o[dt][1]);
        __half2 h1 = __floats2half2_rn(o[dt][2], o[dt][3]);
        *(__half2*)(ctx + base0 + c) = h0;
        *(__half2*)(ctx + base1 + c) = h1;
    }
}

// ---------------------------------------------------------------------------
// hgemm: out[M,Ntot] = A[M,K](fp16) @ Wt[Ntot,K](fp16)^T + bias (+epilogue)
// BM=BN=128, BK=32, 8 warps (2m x 4n), warp tile 64x32, mma.m16n8k16.
// Single barrier per K-iter; B frags via paired ldsm4.
// EPI: 0 fp16 out; 2 gelu -> fp16; 3 fp32 out + rh(zln) + r32(hidden);
//      4 hidden-writer: out32[perm(row)] = acc + bias + rh[row](xw)
//                                          + r32[perm(row)](shortcut)
// ---------------------------------------------------------------------------
#define APITCH   80
#define TILE_B   (128 * APITCH)
#define STAGE_B  (2 * TILE_B)
#define NSTAGE   4
#define SMEM_T   (NSTAGE * STAGE_B)

__device__ __forceinline__ void load_stage(uint32_t sm, int stage,
                                           const __half* A, const __half* Bt,
                                           int K, int m0, int n0, int kk, int t) {
    uint32_t ab = sm + stage * STAGE_B;
    uint32_t bb = ab + TILE_B;
    #pragma unroll
    for (int i = 0; i < 2; i++) {
        int f = t + i * 256;
        int row = f >> 2, seg = f & 3;
        cp16(ab + row * APITCH + seg * 16, A + (size_t)(m0 + row) * K + kk + seg * 8);
    }
    #pragma unroll
    for (int i = 0; i < 2; i++) {
        int f = t + i * 256;
        int row = f >> 2, seg = f & 3;
        cp16(bb + row * APITCH + seg * 16, Bt + (size_t)(n0 + row) * K + kk + seg * 8);
    }
    CP_COMMIT();
}

__device__ __forceinline__ int perm_row(int R) {
    int s = R >> 11, n = R & 2047;
    int hn = s >> 3, wn = s & 7;
    int i = n >> 8, j = (n >> 5) & 7, b = n & 31;
    int h = ((hn << 3) + i + 4) & 63;
    int w = ((wn << 3) + j + 4) & 63;
    return ((h << 6) + w) * 32 + b;
}

template<int EPI>
__global__ void __launch_bounds__(256) hgemm(
    const __half* __restrict__ A, const __half* __restrict__ Bt,
    const float* __restrict__ bias,
    const float* __restrict__ r32, const __half* __restrict__ rh,
    float* __restrict__ out32, __half* __restrict__ outh,
    int Ntot, int K)
{
    extern __shared__ char smem[];
    uint32_t sm = smem_u32(smem);
    int t = threadIdx.x;
    int lane = t & 31, wid = t >> 5;
    int wm = wid & 1, wn = wid >> 1;
    int m0 = blockIdx.y * 128;
    int n0 = blockIdx.x * 128;
    int NI = K / 32;

    float d[4][4][4];
    #pragma unroll
    for (int a = 0; a < 4; a++)
        #pragma unroll
        for (int b = 0; b < 4; b++)
            #pragma unroll
            for (int c = 0; c < 4; c++) d[a][b][c] = 0.0f;

    load_stage(sm, 0, A, Bt, K, m0, n0, 0, t);
    load_stage(sm, 1, A, Bt, K, m0, n0, 32, t);
    load_stage(sm, 2, A, Bt, K, m0, n0, 64, t);

    for (int it = 0; it < NI; it++) {
        cp_wait<2>();
        __syncthreads();
        // All warps are past iter it-1's fragment reads of stage (it+3)&3,
        // so it's safe to refill it now (cutlass multistage pattern).
        if (it + 3 < NI) load_stage(sm, (it + 3) & 3, A, Bt, K, m0, n0, (it + 3) * 32, t);
        else CP_COMMIT();

        uint32_t ab = sm + (it & 3) * STAGE_B;
        uint32_t bb = ab + TILE_B;
        #pragma unroll
        for (int ks = 0; ks < 2; ks++) {
            uint32_t af[4][4], bf[4][2];
            #pragma unroll
            for (int mt = 0; mt < 4; mt++) {
                int row = wm * 64 + mt * 16 + (lane & 15);
                int seg = ks * 2 + (lane >> 4);
                ldsm4(af[mt], ab + row * APITCH + seg * 16);
            }
            {
                int g = lane >> 3;
                #pragma unroll
                for (int np = 0; np < 2; np++) {
                    uint32_t tmp[4];
                    int row = wn * 32 + np * 16 + (g >> 1) * 8 + (lane & 7);
                    int seg = ks * 2 + (g & 1);
                    ldsm4(tmp, bb + row * APITCH + seg * 16);
                    bf[np*2][0]   = tmp[0]; bf[np*2][1]   = tmp[1];
                    bf[np*2+1][0] = tmp[2]; bf[np*2+1][1] = tmp[3];
                }
            }
            #pragma unroll
            for (int mt = 0; mt < 4; mt++)
                #pragma unroll
                for (int nt = 0; nt < 4; nt++)
                    mma16816(d[mt][nt], af[mt], bf[nt]);
        }
        // no end-of-iter barrier: next iter's top barrier provides the fence
    }

    // ---------------- epilogue ----------------
    #pragma unroll
    for (int mt = 0; mt < 4; mt++) {
        int r0 = m0 + wm * 64 + mt * 16 + (lane >> 2);
        #pragma unroll
        for (int hf = 0; hf < 2; hf++) {
            int R = r0 + hf * 8;
            size_t gr = (size_t)R * Ntot;
            size_t pr = (EPI == 4) ? (size_t)perm_row(R) * Ntot : 0;
            #pragma unroll
            for (int nt = 0; nt < 4; nt++) {
                int c = n0 + wn * 32 + nt * 8 + (lane & 3) * 2;
                float2 bv = *(const float2*)(bias + c);
                float x = d[mt][nt][hf * 2 + 0] + bv.x;
                float y = d[mt][nt][hf * 2 + 1] + bv.y;
                if (EPI == 0) {
                    *(__half2*)(outh + gr + c) = __floats2half2_rn(x, y);
                } else if (EPI == 2) {
                    *(__half2*)(outh + gr + c) = __floats2half2_rn(gelu_exact(x), gelu_exact(y));
                } else if (EPI == 3) {
                    float2 rv = __half22float2(*(const __half2*)(rh + gr + c));
                    float2 hv = *(const float2*)(r32 + gr + c);
                    float2 o = {x + rv.x + hv.x, y + rv.y + hv.y};
                    *(float2*)(out32 + gr + c) = o;
                } else {  // EPI == 4
                    float2 rv = __half22float2(*(const __half2*)(rh + gr + c));
                    float2 sv = *(const float2*)(r32 + pr + c);
                    float2 o = {x + rv.x + sv.x, y + rv.y + sv.y};
                    *(float2*)(out32 + pr + c) = o;
                }
            }
        }
    }
}

// ---------------------------------------------------------------------------
// Launch
// ---------------------------------------------------------------------------
extern "C" void kernel_launch(void* const* d_in, const int* in_sizes, int n_in,
                              void* d_out, int out_size) {
    const float* hs    = (const float*)d_in[0];
    const float* ln1g  = (const float*)d_in[1];
    const float* ln1b  = (const float*)d_in[2];
    const float* wqkv  = (const float*)d_in[3];
    const float* bqkv  = (const float*)d_in[4];
    const float* wproj = (const float*)d_in[5];
    const float* bproj = (const float*)d_in[6];
    const float* ln2g  = (const float*)d_in[7];
    const float* ln2b  = (const float*)d_in[8];
    const float* wfc1  = (const float*)d_in[9];
    const float* bfc1  = (const float*)d_in[10];
    const float* wfc2  = (const float*)d_in[11];
    const float* bfc2  = (const float*)d_in[12];
    float* out = (float*)d_out;

    __half *p_xw, *p_qkv, *p_ctx, *p_zln, *p_fc1, *p_wq, *p_wp, *p_w1, *p_w2;
    float *p_hid;
    cudaGetSymbolAddress((void**)&p_xw,  g_xw);
    cudaGetSymbolAddress((void**)&p_qkv, g_qkv);
    cudaGetSymbolAddress((void**)&p_ctx, g_ctx);
    cudaGetSymbolAddress((void**)&p_hid, g_hid);
    cudaGetSymbolAddress((void**)&p_zln, g_zln);
    cudaGetSymbolAddress((void**)&p_fc1, g_fc1);
    cudaGetSymbolAddress((void**)&p_wq,  g_wq);
    cudaGetSymbolAddress((void**)&p_wp,  g_wp);
    cudaGetSymbolAddress((void**)&p_w1,  g_w1);
    cudaGetSymbolAddress((void**)&p_w2,  g_w2);

    cudaFuncSetAttribute(hgemm<0>, cudaFuncAttributeMaxDynamicSharedMemorySize, SMEM_T);
    cudaFuncSetAttribute(hgemm<2>, cudaFuncAttributeMaxDynamicSharedMemorySize, SMEM_T);
    cudaFuncSetAttribute(hgemm<3>, cudaFuncAttributeMaxDynamicSharedMemorySize, SMEM_T);
    cudaFuncSetAttribute(hgemm<4>, cudaFuncAttributeMaxDynamicSharedMemorySize, SMEM_T);

    // fused weight transpose -> fp16 [N][K]
    wprep_all<<<3072, 256>>>(wqkv, wproj, wfc1, wfc2, p_wq, p_wp, p_w1, p_w2);

    // LN1 + shift + partition (warp-per-row)
    ln_shift_warp<<<2048, 256>>>(hs, ln1g, ln1b, p_xw);

    // qkv = xw @ Wqkv + b           -> fp16
    hgemm<0><<<dim3(12, 1024), 256, SMEM_T>>>(p_xw, p_wq, bqkv,
        nullptr, nullptr, nullptr, p_qkv, 1536, 512);

    // attention (HMMA)
    attn_kernel<<<dim3(2048, 8), 256>>>(p_qkv, p_ctx);

    // hidden[perm] = ctx @ Wproj + b + xw + shortcut[perm]   (fused reverse)
    hgemm<4><<<dim3(4, 1024), 256, SMEM_T>>>(p_ctx, p_wp, bproj,
        hs, p_xw, p_hid, nullptr, 512, 512);

    // zln = LN2(hidden)  (warp-per-row)
    ln2_warp<<<2048, 256>>>(p_hid, ln2g, ln2b, p_zln);

    // fc1 = gelu(zln @ Wfc1 + b)    -> fp16
    hgemm<2><<<dim3(16, 1024), 256, SMEM_T>>>(p_zln, p_w1, bfc1,
        nullptr, nullptr, nullptr, p_fc1, 2048, 512);

    // out = fc1 @ Wfc2 + b + zln + hidden
    hgemm<3><<<dim3(4, 1024), 256, SMEM_T>>>(p_fc1, p_w2, bfc2,
        p_hid, p_zln, out, nullptr, 512, 2048);
}

// round 16
// speedup vs baseline: 1.1059x; 1.0826x over previous
#include <cuda_runtime.h>
#include <cuda_fp16.h>
#include <cstdint>
#include <cstddef>

// ===========================================================================
// SwinBlock_tp on GB300 — fp16 mma.sync GEMMs (BM=BN=128, warp 64x32,
// BK=64, 3-stage, 2 CTA/SM, single-barrier mainloop) + HMMA attention
// (occupancy-boosted) + warp-per-row LN.  M = 131072 rows, C = 512.
// ===========================================================================

#define MROWS 131072

// ------------------------- scratch (device globals) ------------------------
__device__ __half g_xw [(size_t)MROWS * 512];
__device__ __half g_qkv[(size_t)MROWS * 1536];
__device__ __half g_ctx[(size_t)MROWS * 512];
__device__ float  g_hid [(size_t)MROWS * 512];
__device__ __half g_zln[(size_t)MROWS * 512];
__device__ __half g_fc1[(size_t)MROWS * 2048];
// transposed weights [N][K] fp16
__device__ __half g_wq[1536 * 512];
__device__ __half g_wp[512 * 512];
__device__ __half g_w1[2048 * 512];
__device__ __half g_w2[512 * 2048];

// ------------------------------ PTX helpers --------------------------------
__device__ __forceinline__ uint32_t smem_u32(const void* p) {
    uint32_t a;
    asm("{ .reg .u64 t; cvta.to.shared.u64 t, %1; cvt.u32.u64 %0, t; }" : "=r"(a) : "l"(p));
    return a;
}
__device__ __forceinline__ void cp16(uint32_t dst, const void* src) {
    asm volatile("cp.async.cg.shared.global [%0], [%1], 16;\n" :: "r"(dst), "l"(src) : "memory");
}
#define CP_COMMIT() asm volatile("cp.async.commit_group;\n" ::: "memory")
template<int N> __device__ __forceinline__ void cp_wait() {
    asm volatile("cp.async.wait_group %0;\n" :: "n"(N) : "memory");
}
__device__ __forceinline__ void ldsm4(uint32_t* r, uint32_t addr) {
    asm volatile("ldmatrix.sync.aligned.m8n8.x4.shared.b16 {%0,%1,%2,%3}, [%4];"
        : "=r"(r[0]), "=r"(r[1]), "=r"(r[2]), "=r"(r[3]) : "r"(addr));
}
__device__ __forceinline__ void ldsm4t(uint32_t* r, uint32_t addr) {
    asm volatile("ldmatrix.sync.aligned.m8n8.x4.trans.shared.b16 {%0,%1,%2,%3}, [%4];"
        : "=r"(r[0]), "=r"(r[1]), "=r"(r[2]), "=r"(r[3]) : "r"(addr));
}
__device__ __forceinline__ void mma16816(float* d, const uint32_t* a, const uint32_t* b) {
    asm volatile("mma.sync.aligned.m16n8k16.row.col.f32.f16.f16.f32 "
        "{%0,%1,%2,%3}, {%4,%5,%6,%7}, {%8,%9}, {%0,%1,%2,%3};"
        : "+f"(d[0]), "+f"(d[1]), "+f"(d[2]), "+f"(d[3])
        : "r"(a[0]), "r"(a[1]), "r"(a[2]), "r"(a[3]), "r"(b[0]), "r"(b[1]));
}

// ------------------------------ small helpers ------------------------------
__device__ __forceinline__ float gelu_exact(float x) {
    return 0.5f * x * (1.0f + erff(x * 0.70710678118654752f));
}
__device__ __forceinline__ void warp_reduce2(float& sum, float& sq) {
    #pragma unroll
    for (int o = 16; o > 0; o >>= 1) {
        sum += __shfl_xor_sync(0xffffffffu, sum, o);
        sq  += __shfl_xor_sync(0xffffffffu, sq,  o);
    }
}

// ---------------------------------------------------------------------------
// K0: fused weight transpose  W[K,N] -> Wt[N,K] fp16, all 4 weights, 1 launch
// ---------------------------------------------------------------------------
__global__ void wprep_all(const float* __restrict__ Wq, const float* __restrict__ Wp,
                          const float* __restrict__ W1, const float* __restrict__ W2,
                          __half* __restrict__ Tq, __half* __restrict__ Tp,
                          __half* __restrict__ T1, __half* __restrict__ T2) {
    __shared__ float tile[32][33];
    int id = blockIdx.x;
    const float* W; __half* T; int K, N, nb, kb;
    if (id < 768)       { W = Wq; T = Tq; K = 512;  N = 1536; int r = id;        nb = (r % 48) * 32; kb = (r / 48) * 32; }
    else if (id < 1024) { W = Wp; T = Tp; K = 512;  N = 512;  int r = id - 768;  nb = (r % 16) * 32; kb = (r / 16) * 32; }
    else if (id < 2048) { W = W1; T = T1; K = 512;  N = 2048; int r = id - 1024; nb = (r % 64) * 32; kb = (r / 64) * 32; }
    else                { W = W2; T = T2; K = 2048; N = 512;  int r = id - 2048; nb = (r % 16) * 32; kb = (r / 16) * 32; }

    int tx = threadIdx.x & 31, ty = threadIdx.x >> 5;
    #pragma unroll
    for (int i = ty; i < 32; i += 8)
        tile[i][tx] = W[(size_t)(kb + i) * N + nb + tx];
    __syncthreads();
    #pragma unroll
    for (int i = ty; i < 32; i += 8)
        T[(size_t)(nb + i) * K + kb + tx] = __float2half(tile[tx][i]);
}

// ---------------------------------------------------------------------------
// K1: LN1 + roll(-4,-4) + window partition -> fp16.  Warp-per-row.
// ---------------------------------------------------------------------------
__global__ __launch_bounds__(256) void ln_shift_warp(const float* __restrict__ x,
                                                     const float* __restrict__ g,
                                                     const float* __restrict__ b,
                                                     __half* __restrict__ out) {
    int wg = (blockIdx.x * 256 + threadIdx.x) >> 5;
    int lane = threadIdx.x & 31;

    float4 gv[4], bv[4];
    #pragma unroll
    for (int k = 0; k < 4; k++) {
        gv[k] = *(const float4*)(g + (k * 32 + lane) * 4);
        bv[k] = *(const float4*)(b + (k * 32 + lane) * 4);
    }

    #pragma unroll
    for (int rw = 0; rw < 8; rw++) {
        int r = wg * 8 + rw;
        int s = r >> 11, n = r & 2047;
        int hn = s >> 3, wn = s & 7;
        int i = n >> 8, j = (n >> 5) & 7, bb = n & 31;
        int h = ((hn << 3) + i + 4) & 63;
        int w = ((wn << 3) + j + 4) & 63;
        size_t src = ((size_t)((h << 6) + w) * 32 + bb) * 512;

        float4 v[4];
        float sum = 0.0f, sq = 0.0f;
        #pragma unroll
        for (int k = 0; k < 4; k++) {
            v[k] = *(const float4*)(x + src + (k * 32 + lane) * 4);
            sum += v[k].x + v[k].y + v[k].z + v[k].w;
            sq  += v[k].x*v[k].x + v[k].y*v[k].y + v[k].z*v[k].z + v[k].w*v[k].w;
        }
        warp_reduce2(sum, sq);
        float mu = sum * (1.0f/512.0f);
        float rstd = rsqrtf(sq * (1.0f/512.0f) - mu*mu + 1e-5f);

        size_t dst = (size_t)r * 512;
        #pragma unroll
        for (int k = 0; k < 4; k++) {
            __half2 h0 = __floats2half2_rn((v[k].x - mu)*rstd*gv[k].x + bv[k].x,
                                           (v[k].y - mu)*rstd*gv[k].y + bv[k].y);
            __half2 h1 = __floats2half2_rn((v[k].z - mu)*rstd*gv[k].z + bv[k].z,
                                           (v[k].w - mu)*rstd*gv[k].w + bv[k].w);
            uint2 u; u.x = *(uint32_t*)&h0; u.y = *(uint32_t*)&h1;
            *(uint2*)(out + dst + (k * 32 + lane) * 4) = u;
        }
    }
}

// ---------------------------------------------------------------------------
// K5b: LN2 over fp32 hidden (token domain) -> zln fp16.  Warp-per-row.
// ---------------------------------------------------------------------------
__global__ __launch_bounds__(256) void ln2_warp(const float* __restrict__ hid,
                                                const float* __restrict__ g,
                                                const float* __restrict__ b,
                                                __half* __restrict__ zln) {
    int wg = (blockIdx.x * 256 + threadIdx.x) >> 5;
    int lane = threadIdx.x & 31;

    float4 gv[4], bv[4];
    #pragma unroll
    for (int k = 0; k < 4; k++) {
        gv[k] = *(const float4*)(g + (k * 32 + lane) * 4);
        bv[k] = *(const float4*)(b + (k * 32 + lane) * 4);
    }

    #pragma unroll
    for (int rw = 0; rw < 8; rw++) {
        int m = wg * 8 + rw;
        size_t src = (size_t)m * 512;
        float4 v[4];
        float sum = 0.0f, sq = 0.0f;
        #pragma unroll
        for (int k = 0; k < 4; k++) {
            v[k] = *(const float4*)(hid + src + (k * 32 + lane) * 4);
            sum += v[k].x + v[k].y + v[k].z + v[k].w;
            sq  += v[k].x*v[k].x + v[k].y*v[k].y + v[k].z*v[k].z + v[k].w*v[k].w;
        }
        warp_reduce2(sum, sq);
        float mu = sum * (1.0f/512.0f);
        float rstd = rsqrtf(sq * (1.0f/512.0f) - mu*mu + 1e-5f);

        #pragma unroll
        for (int k = 0; k < 4; k++) {
            __half2 h0 = __floats2half2_rn((v[k].x - mu)*rstd*gv[k].x + bv[k].x,
                                           (v[k].y - mu)*rstd*gv[k].y + bv[k].y);
            __half2 h1 = __floats2half2_rn((v[k].z - mu)*rstd*gv[k].z + bv[k].z,
                                           (v[k].w - mu)*rstd*gv[k].w + bv[k].w);
            uint2 u; u.x = *(uint32_t*)&h0; u.y = *(uint32_t*)&h1;
            *(uint2*)(zln + src + (k * 32 + lane) * 4) = u;
        }
    }
}

// ---------------------------------------------------------------------------
// K3: HMMA attention. CTA = (n, head-pair): 256 threads, 8 warps.
// __launch_bounds__(256,5): cap regs ~51 to lift occupancy 4 -> 5 CTAs/SM.
// ---------------------------------------------------------------------------
__device__ __forceinline__ int region_id(int c) { return c < 56 ? 0 : (c < 60 ? 1 : 2); }

#define ATT_PITCH 80
#define ATT_TILE  (64 * ATT_PITCH)

__global__ __launch_bounds__(256, 5) void attn_kernel(const __half* __restrict__ qkv,
                                                      __half* __restrict__ ctx) {
    __shared__ __half sAll[2][3][64 * 40];
    __shared__ int val[64];

    const int n = blockIdx.x, t = threadIdx.x;
    const int lane = t & 31, wid = t >> 5;
    const int hg = wid >> 2, w = wid & 3;
    const int h = blockIdx.y * 2 + hg;
    const uint32_t sbase = smem_u32(&sAll[0][0][0]);

    #pragma unroll
    for (int i = 0; i < 6; i++) {
        int f = t + i * 256;
        int hg2  = f / 768;
        int rem  = f - hg2 * 768;
        int part = rem >> 8;
        int rr   = rem & 255;
        int row  = rr >> 2, seg = rr & 3;
        const __half* src = qkv + (size_t)(row * 2048 + n) * 1536
                          + (blockIdx.y * 2 + hg2) * 96 + part * 32 + seg * 8;
        cp16(sbase + (hg2 * 3 + part) * ATT_TILE + row * ATT_PITCH + seg * 16, src);
    }
    CP_COMMIT();
    if (t < 64) {
        int mw = n & 63;
        int hh = ((mw >> 3) << 3) + (t >> 3);
        int ww = ((mw & 7) << 3) + (t & 7);
        val[t] = region_id(hh) * 3 + region_id(ww);
    }
    cp_wait<0>();
    __syncthreads();

    const uint32_t qb = sbase + (hg * 3 + 0) * ATT_TILE;
    const uint32_t kb = sbase + (hg * 3 + 1) * ATT_TILE;
    const uint32_t vb = sbase + (hg * 3 + 2) * ATT_TILE;

    float d[8][4];
    #pragma unroll
    for (int nt = 0; nt < 8; nt++)
        #pragma unroll
        for (int j = 0; j < 4; j++) d[nt][j] = 0.0f;

    #pragma unroll
    for (int ks = 0; ks < 2; ks++) {
        uint32_t af[4];
        ldsm4(af, qb + (w * 16 + (lane & 15)) * ATT_PITCH + (ks * 2 + (lane >> 4)) * 16);
        uint32_t bf[8][2];
        int g = lane >> 3;
        #pragma unroll
        for (int np = 0; np < 4; np++) {
            uint32_t tmp[4];
            ldsm4(tmp, kb + (np * 16 + (g >> 1) * 8 + (lane & 7)) * ATT_PITCH
                          + (ks * 2 + (g & 1)) * 16);
            bf[np*2][0]   = tmp[0]; bf[np*2][1]   = tmp[1];
            bf[np*2+1][0] = tmp[2]; bf[np*2+1][1] = tmp[3];
        }
        #pragma unroll
        for (int nt = 0; nt < 8; nt++) mma16816(d[nt], af, bf[nt]);
    }

    const int r0 = lane >> 2;
    const int c0 = 2 * (lane & 3);
    const int vs0 = val[w * 16 + r0];
    const int vs1 = val[w * 16 + r0 + 8];
    const float SCALE = 0.17677669529663687f;

    float mx0 = -1e30f, mx1 = -1e30f;
    #pragma unroll
    for (int nt = 0; nt < 8; nt++) {
        int vc0 = val[nt * 8 + c0], vc1 = val[nt * 8 + c0 + 1];
        d[nt][0] = (vc0 != vs0) ? -10000.0f : d[nt][0] * SCALE;
        d[nt][1] = (vc1 != vs0) ? -10000.0f : d[nt][1] * SCALE;
        d[nt][2] = (vc0 != vs1) ? -10000.0f : d[nt][2] * SCALE;
        d[nt][3] = (vc1 != vs1) ? -10000.0f : d[nt][3] * SCALE;
        mx0 = fmaxf(mx0, fmaxf(d[nt][0], d[nt][1]));
        mx1 = fmaxf(mx1, fmaxf(d[nt][2], d[nt][3]));
    }
    mx0 = fmaxf(mx0, __shfl_xor_sync(0xffffffffu, mx0, 1));
    mx0 = fmaxf(mx0, __shfl_xor_sync(0xffffffffu, mx0, 2));
    mx1 = fmaxf(mx1, __shfl_xor_sync(0xffffffffu, mx1, 1));
    mx1 = fmaxf(mx1, __shfl_xor_sync(0xffffffffu, mx1, 2));

    float s0 = 0.0f, s1 = 0.0f;
    #pragma unroll
    for (int nt = 0; nt < 8; nt++) {
        d[nt][0] = __expf(d[nt][0] - mx0);
        d[nt][1] = __expf(d[nt][1] - mx0);
        d[nt][2] = __expf(d[nt][2] - mx1);
        d[nt][3] = __expf(d[nt][3] - mx1);
        s0 += d[nt][0] + d[nt][1];
        s1 += d[nt][2] + d[nt][3];
    }
    s0 += __shfl_xor_sync(0xffffffffu, s0, 1);
    s0 += __shfl_xor_sync(0xffffffffu, s0, 2);
    s1 += __shfl_xor_sync(0xffffffffu, s1, 1);
    s1 += __shfl_xor_sync(0xffffffffu, s1, 2);
    const float inv0 = 1.0f / s0, inv1 = 1.0f / s1;

    uint32_t pf[4][4];
    #pragma unroll
    for (int kt = 0; kt < 4; kt++) {
        __half2 a0 = __floats2half2_rn(d[2*kt][0]   * inv0, d[2*kt][1]   * inv0);
        __half2 a1 = __floats2half2_rn(d[2*kt][2]   * inv1, d[2*kt][3]   * inv1);
        __half2 a2 = __floats2half2_rn(d[2*kt+1][0] * inv0, d[2*kt+1][1] * inv0);
        __half2 a3 = __floats2half2_rn(d[2*kt+1][2] * inv1, d[2*kt+1][3] * inv1);
        pf[kt][0] = *(uint32_t*)&a0; pf[kt][1] = *(uint32_t*)&a1;
        pf[kt][2] = *(uint32_t*)&a2; pf[kt][3] = *(uint32_t*)&a3;
    }

    float o[4][4];
    #pragma unroll
    for (int dt = 0; dt < 4; dt++)
        #pragma unroll
        for (int j = 0; j < 4; j++) o[dt][j] = 0.0f;

    {
        int g = lane >> 3;
        #pragma unroll
        for (int kt = 0; kt < 4; kt++) {
            uint32_t bv[4][2];
            #pragma unroll
            for (int dp = 0; dp < 2; dp++) {
                uint32_t tmp[4];
                ldsm4t(tmp, vb + (kt * 16 + (g & 1) * 8 + (lane & 7)) * ATT_PITCH
                               + dp * 32 + (g >> 1) * 16);
                bv[dp*2][0]   = tmp[0]; bv[dp*2][1]   = tmp[1];
                bv[dp*2+1][0] = tmp[2]; bv[dp*2+1][1] = tmp[3];
            }
            #pragma unroll
            for (int dt = 0; dt < 4; dt++) mma16816(o[dt], pf[kt], bv[dt]);
        }
    }

    const int srow0 = w * 16 + r0;
    const size_t base0 = (size_t)(srow0 * 2048 + n) * 512 + h * 32;
    const size_t base1 = (size_t)((srow0 + 8) * 2048 + n) * 512 + h * 32;
    #pragma unroll
    for (int dt = 0; dt < 4; dt++) {
        int c = dt * 8 + c0;
        __half2 h0 = __floats2half2_rn(o[dt][0], o[dt][1]);
        __half2 h1 = __floats2half2_rn(o[dt][2], o[dt][3]);
        *(__half2*)(ctx + base0 + c) = h0;
        *(__half2*)(ctx + base1 + c) = h1;
    }
}

// ---------------------------------------------------------------------------
// hgemm: out[M,Ntot] = A[M,K](fp16) @ Wt[Ntot,K](fp16)^T + bias (+epilogue)
// BM=BN=128, BK=64, 3 stages, 8 warps (2m x 4n), warp tile 64x32.
// pitch 144B: 8-row ldsm groups hit offsets r*16 mod 128 -> conflict-free.
// Single barrier per K-iter (half as many iters as BK=32).
// EPI: 0 fp16 out; 2 gelu -> fp16; 3 fp32 out + rh(zln) + r32(hidden);
//      4 hidden-writer: out32[perm(row)] = acc + bias + rh[row](xw)
//                                          + r32[perm(row)](shortcut)
// ---------------------------------------------------------------------------
#define APITCH   144
#define TILE_B   (128 * APITCH)          // 18432
#define STAGE_B  (2 * TILE_B)            // 36864
#define NSTAGE   3
#define SMEM_T   (NSTAGE * STAGE_B)      // 110592

__device__ __forceinline__ void load_stage(uint32_t sm, int stage,
                                           const __half* A, const __half* Bt,
                                           int K, int m0, int n0, int kk, int t) {
    uint32_t ab = sm + stage * STAGE_B;
    uint32_t bb = ab + TILE_B;
    #pragma unroll
    for (int i = 0; i < 4; i++) {
        int f = t + i * 256;
        int row = f >> 3, seg = f & 7;
        cp16(ab + row * APITCH + seg * 16, A + (size_t)(m0 + row) * K + kk + seg * 8);
    }
    #pragma unroll
    for (int i = 0; i < 4; i++) {
        int f = t + i * 256;
        int row = f >> 3, seg = f & 7;
        cp16(bb + row * APITCH + seg * 16, Bt + (size_t)(n0 + row) * K + kk + seg * 8);
    }
    CP_COMMIT();
}

__device__ __forceinline__ int perm_row(int R) {
    int s = R >> 11, n = R & 2047;
    int hn = s >> 3, wn = s & 7;
    int i = n >> 8, j = (n >> 5) & 7, b = n & 31;
    int h = ((hn << 3) + i + 4) & 63;
    int w = ((wn << 3) + j + 4) & 63;
    return ((h << 6) + w) * 32 + b;
}

template<int EPI>
__global__ void __launch_bounds__(256) hgemm(
    const __half* __restrict__ A, const __half* __restrict__ Bt,
    const float* __restrict__ bias,
    const float* __restrict__ r32, const __half* __restrict__ rh,
    float* __restrict__ out32, __half* __restrict__ outh,
    int Ntot, int K)
{
    extern __shared__ char smem[];
    uint32_t sm = smem_u32(smem);
    int t = threadIdx.x;
    int lane = t & 31, wid = t >> 5;
    int wm = wid & 1, wn = wid >> 1;
    int m0 = blockIdx.y * 128;
    int n0 = blockIdx.x * 128;
    int NI = K / 64;

    float d[4][4][4];
    #pragma unroll
    for (int a = 0; a < 4; a++)
        #pragma unroll
        for (int b = 0; b < 4; b++)
            #pragma unroll
            for (int c = 0; c < 4; c++) d[a][b][c] = 0.0f;

    load_stage(sm, 0, A, Bt, K, m0, n0, 0, t);
    load_stage(sm, 1, A, Bt, K, m0, n0, 64, t);

    int st = 0;                 // stage of iter it (mod 3, tracked incrementally)
    for (int it = 0; it < NI; it++) {
        cp_wait<1>();
        __syncthreads();
        // All warps are past iter it-1's fragment reads of stage (it+2)%3,
        // so it's safe to refill it now.
        int st2 = st + 2 >= 3 ? st - 1 : st + 2;
        if (it + 2 < NI) load_stage(sm, st2, A, Bt, K, m0, n0, (it + 2) * 64, t);
        else CP_COMMIT();

        uint32_t ab = sm + st * STAGE_B;
        uint32_t bb = ab + TILE_B;
        #pragma unroll
        for (int ks = 0; ks < 4; ks++) {
            uint32_t af[4][4], bf[4][2];
            #pragma unroll
            for (int mt = 0; mt < 4; mt++) {
                int row = wm * 64 + mt * 16 + (lane & 15);
                int seg = ks * 2 + (lane >> 4);
                ldsm4(af[mt], ab + row * APITCH + seg * 16);
            }
            {
                int g = lane >> 3;
                #pragma unroll
                for (int np = 0; np < 2; np++) {
                    uint32_t tmp[4];
                    int row = wn * 32 + np * 16 + (g >> 1) * 8 + (lane & 7);
                    int seg = ks * 2 + (g & 1);
                    ldsm4(tmp, bb + row * APITCH + seg * 16);
                    bf[np*2][0]   = tmp[0]; bf[np*2][1]   = tmp[1];
                    bf[np*2+1][0] = tmp[2]; bf[np*2+1][1] = tmp[3];
                }
            }
            #pragma unroll
            for (int mt = 0; mt < 4; mt++)
                #pragma unroll
                for (int nt = 0; nt < 4; nt++)
                    mma16816(d[mt][nt], af[mt], bf[nt]);
        }
        st = st + 1 >= 3 ? 0 : st + 1;
        // no end-of-iter barrier: next iter's top barrier provides the fence
    }

    // ---------------- epilogue ----------------
    #pragma unroll
    for (int mt = 0; mt < 4; mt++) {
        int r0 = m0 + wm * 64 + mt * 16 + (lane >> 2);
        #pragma unroll
        for (int hf = 0; hf < 2; hf++) {
            int R = r0 + hf * 8;
            size_t gr = (size_t)R * Ntot;
            size_t pr = (EPI == 4) ? (size_t)perm_row(R) * Ntot : 0;
            #pragma unroll
            for (int nt = 0; nt < 4; nt++) {
                int c = n0 + wn * 32 + nt * 8 + (lane & 3) * 2;
                float2 bv = *(const float2*)(bias + c);
                float x = d[mt][nt][hf * 2 + 0] + bv.x;
                float y = d[mt][nt][hf * 2 + 1] + bv.y;
                if (EPI == 0) {
                    *(__half2*)(outh + gr + c) = __floats2half2_rn(x, y);
                } else if (EPI == 2) {
                    *(__half2*)(outh + gr + c) = __floats2half2_rn(gelu_exact(x), gelu_exact(y));
                } else if (EPI == 3) {
                    float2 rv = __half22float2(*(const __half2*)(rh + gr + c));
                    float2 hv = *(const float2*)(r32 + gr + c);
                    float2 o = {x + rv.x + hv.x, y + rv.y + hv.y};
                    *(float2*)(out32 + gr + c) = o;
                } else {  // EPI == 4
                    float2 rv = __half22float2(*(const __half2*)(rh + gr + c));
                    float2 sv = *(const float2*)(r32 + pr + c);
                    float2 o = {x + rv.x + sv.x, y + rv.y + sv.y};
                    *(float2*)(out32 + pr + c) = o;
                }
            }
        }
    }
}

// ---------------------------------------------------------------------------
// Launch
// ---------------------------------------------------------------------------
extern "C" void kernel_launch(void* const* d_in, const int* in_sizes, int n_in,
                              void* d_out, int out_size) {
    const float* hs    = (const float*)d_in[0];
    const float* ln1g  = (const float*)d_in[1];
    const float* ln1b  = (const float*)d_in[2];
    const float* wqkv  = (const float*)d_in[3];
    const float* bqkv  = (const float*)d_in[4];
    const float* wproj = (const float*)d_in[5];
    const float* bproj = (const float*)d_in[6];
    const float* ln2g  = (const float*)d_in[7];
    const float* ln2b  = (const float*)d_in[8];
    const float* wfc1  = (const float*)d_in[9];
    const float* bfc1  = (const float*)d_in[10];
    const float* wfc2  = (const float*)d_in[11];
    const float* bfc2  = (const float*)d_in[12];
    float* out = (float*)d_out;

    __half *p_xw, *p_qkv, *p_ctx, *p_zln, *p_fc1, *p_wq, *p_wp, *p_w1, *p_w2;
    float *p_hid;
    cudaGetSymbolAddress((void**)&p_xw,  g_xw);
    cudaGetSymbolAddress((void**)&p_qkv, g_qkv);
    cudaGetSymbolAddress((void**)&p_ctx, g_ctx);
    cudaGetSymbolAddress((void**)&p_hid, g_hid);
    cudaGetSymbolAddress((void**)&p_zln, g_zln);
    cudaGetSymbolAddress((void**)&p_fc1, g_fc1);
    cudaGetSymbolAddress((void**)&p_wq,  g_wq);
    cudaGetSymbolAddress((void**)&p_wp,  g_wp);
    cudaGetSymbolAddress((void**)&p_w1,  g_w1);
    cudaGetSymbolAddress((void**)&p_w2,  g_w2);

    cudaFuncSetAttribute(hgemm<0>, cudaFuncAttributeMaxDynamicSharedMemorySize, SMEM_T);
    cudaFuncSetAttribute(hgemm<2>, cudaFuncAttributeMaxDynamicSharedMemorySize, SMEM_T);
    cudaFuncSetAttribute(hgemm<3>, cudaFuncAttributeMaxDynamicSharedMemorySize, SMEM_T);
    cudaFuncSetAttribute(hgemm<4>, cudaFuncAttributeMaxDynamicSharedMemorySize, SMEM_T);

    // fused weight transpose -> fp16 [N][K]
    wprep_all<<<3072, 256>>>(wqkv, wproj, wfc1, wfc2, p_wq, p_wp, p_w1, p_w2);

    // LN1 + shift + partition (warp-per-row)
    ln_shift_warp<<<2048, 256>>>(hs, ln1g, ln1b, p_xw);

    // qkv = xw @ Wqkv + b           -> fp16
    hgemm<0><<<dim3(12, 1024), 256, SMEM_T>>>(p_xw, p_wq, bqkv,
        nullptr, nullptr, nullptr, p_qkv, 1536, 512);

    // attention (HMMA)
    attn_kernel<<<dim3(2048, 8), 256>>>(p_qkv, p_ctx);

    // hidden[perm] = ctx @ Wproj + b + xw + shortcut[perm]   (fused reverse)
    hgemm<4><<<dim3(4, 1024), 256, SMEM_T>>>(p_ctx, p_wp, bproj,
        hs, p_xw, p_hid, nullptr, 512, 512);

    // zln = LN2(hidden)  (warp-per-row)
    ln2_warp<<<2048, 256>>>(p_hid, ln2g, ln2b, p_zln);

    // fc1 = gelu(zln @ Wfc1 + b)    -> fp16
    hgemm<2><<<dim3(16, 1024), 256, SMEM_T>>>(p_zln, p_w1, bfc1,
        nullptr, nullptr, nullptr, p_fc1, 2048, 512);

    // out = fc1 @ Wfc2 + b + zln + hidden
    hgemm<3><<<dim3(4, 1024), 256, SMEM_T>>>(p_fc1, p_w2, bfc2,
        p_hid, p_zln, out, nullptr, 512, 2048);
}

// round 17
// speedup vs baseline: 1.1077x; 1.0017x over previous
#include <cuda_runtime.h>
#include <cuda_fp16.h>
#include <cstdint>
#include <cstddef>

// ===========================================================================
// SwinBlock_tp on GB300 — fp16 mma.sync GEMMs (BM=BN=128, warp 64x32,
// BK=64, 3-stage, 2 CTA/SM) + HMMA attention + warp-per-row LN + PDL
// overlap across the kernel chain.  M = 131072 rows, C = 512.
// ===========================================================================

#define MROWS 131072

// ------------------------- scratch (device globals) ------------------------
__device__ __half g_xw [(size_t)MROWS * 512];
__device__ __half g_qkv[(size_t)MROWS * 1536];
__device__ __half g_ctx[(size_t)MROWS * 512];
__device__ float  g_hid [(size_t)MROWS * 512];
__device__ __half g_zln[(size_t)MROWS * 512];
__device__ __half g_fc1[(size_t)MROWS * 2048];
// transposed weights [N][K] fp16
__device__ __half g_wq[1536 * 512];
__device__ __half g_wp[512 * 512];
__device__ __half g_w1[2048 * 512];
__device__ __half g_w2[512 * 2048];

// ------------------------------ PTX helpers --------------------------------
__device__ __forceinline__ uint32_t smem_u32(const void* p) {
    uint32_t a;
    asm("{ .reg .u64 t; cvta.to.shared.u64 t, %1; cvt.u32.u64 %0, t; }" : "=r"(a) : "l"(p));
    return a;
}
__device__ __forceinline__ void cp16(uint32_t dst, const void* src) {
    asm volatile("cp.async.cg.shared.global [%0], [%1], 16;\n" :: "r"(dst), "l"(src) : "memory");
}
#define CP_COMMIT() asm volatile("cp.async.commit_group;\n" ::: "memory")
template<int N> __device__ __forceinline__ void cp_wait() {
    asm volatile("cp.async.wait_group %0;\n" :: "n"(N) : "memory");
}
__device__ __forceinline__ void gdc_wait()   { asm volatile("griddepcontrol.wait;" ::: "memory"); }
__device__ __forceinline__ void gdc_launch() { asm volatile("griddepcontrol.launch_dependents;" ::: "memory"); }
__device__ __forceinline__ void ldsm4(uint32_t* r, uint32_t addr) {
    asm volatile("ldmatrix.sync.aligned.m8n8.x4.shared.b16 {%0,%1,%2,%3}, [%4];"
        : "=r"(r[0]), "=r"(r[1]), "=r"(r[2]), "=r"(r[3]) : "r"(addr));
}
__device__ __forceinline__ void ldsm4t(uint32_t* r, uint32_t addr) {
    asm volatile("ldmatrix.sync.aligned.m8n8.x4.trans.shared.b16 {%0,%1,%2,%3}, [%4];"
        : "=r"(r[0]), "=r"(r[1]), "=r"(r[2]), "=r"(r[3]) : "r"(addr));
}
__device__ __forceinline__ void mma16816(float* d, const uint32_t* a, const uint32_t* b) {
    asm volatile("mma.sync.aligned.m16n8k16.row.col.f32.f16.f16.f32 "
        "{%0,%1,%2,%3}, {%4,%5,%6,%7}, {%8,%9}, {%0,%1,%2,%3};"
        : "+f"(d[0]), "+f"(d[1]), "+f"(d[2]), "+f"(d[3])
        : "r"(a[0]), "r"(a[1]), "r"(a[2]), "r"(a[3]), "r"(b[0]), "r"(b[1]));
}

// ------------------------------ small helpers ------------------------------
__device__ __forceinline__ float gelu_exact(float x) {
    return 0.5f * x * (1.0f + erff(x * 0.70710678118654752f));
}
__device__ __forceinline__ void warp_reduce2(float& sum, float& sq) {
    #pragma unroll
    for (int o = 16; o > 0; o >>= 1) {
        sum += __shfl_xor_sync(0xffffffffu, sum, o);
        sq  += __shfl_xor_sync(0xffffffffu, sq,  o);
    }
}

// ---------------------------------------------------------------------------
// K0: fused weight transpose  W[K,N] -> Wt[N,K] fp16, all 4 weights, 1 launch
// ---------------------------------------------------------------------------
__global__ void wprep_all(const float* __restrict__ Wq, const float* __restrict__ Wp,
                          const float* __restrict__ W1, const float* __restrict__ W2,
                          __half* __restrict__ Tq, __half* __restrict__ Tp,
                          __half* __restrict__ T1, __half* __restrict__ T2) {
    __shared__ float tile[32][33];
    int id = blockIdx.x;
    const float* W; __half* T; int K, N, nb, kb;
    if (id < 768)       { W = Wq; T = Tq; K = 512;  N = 1536; int r = id;        nb = (r % 48) * 32; kb = (r / 48) * 32; }
    else if (id < 1024) { W = Wp; T = Tp; K = 512;  N = 512;  int r = id - 768;  nb = (r % 16) * 32; kb = (r / 16) * 32; }
    else if (id < 2048) { W = W1; T = T1; K = 512;  N = 2048; int r = id - 1024; nb = (r % 64) * 32; kb = (r / 64) * 32; }
    else                { W = W2; T = T2; K = 2048; N = 512;  int r = id - 2048; nb = (r % 16) * 32; kb = (r / 16) * 32; }

    int tx = threadIdx.x & 31, ty = threadIdx.x >> 5;
    #pragma unroll
    for (int i = ty; i < 32; i += 8)
        tile[i][tx] = W[(size_t)(kb + i) * N + nb + tx];
    __syncthreads();
    #pragma unroll
    for (int i = ty; i < 32; i += 8)
        T[(size_t)(nb + i) * K + kb + tx] = __float2half(tile[tx][i]);
    gdc_launch();
}

// ---------------------------------------------------------------------------
// K1: LN1 + roll(-4,-4) + window partition -> fp16.  Warp-per-row.
// Reads only harness inputs -> waits at the END (full overlap with wprep;
// PDL induction still guarantees wprep complete once this grid completes).
// ---------------------------------------------------------------------------
__global__ __launch_bounds__(256) void ln_shift_warp(const float* __restrict__ x,
                                                     const float* __restrict__ g,
                                                     const float* __restrict__ b,
                                                     __half* __restrict__ out) {
    int wg = (blockIdx.x * 256 + threadIdx.x) >> 5;
    int lane = threadIdx.x & 31;

    float4 gv[4], bv[4];
    #pragma unroll
    for (int k = 0; k < 4; k++) {
        gv[k] = *(const float4*)(g + (k * 32 + lane) * 4);
        bv[k] = *(const float4*)(b + (k * 32 + lane) * 4);
    }

    #pragma unroll
    for (int rw = 0; rw < 8; rw++) {
        int r = wg * 8 + rw;
        int s = r >> 11, n = r & 2047;
        int hn = s >> 3, wn = s & 7;
        int i = n >> 8, j = (n >> 5) & 7, bb = n & 31;
        int h = ((hn << 3) + i + 4) & 63;
        int w = ((wn << 3) + j + 4) & 63;
        size_t src = ((size_t)((h << 6) + w) * 32 + bb) * 512;

        float4 v[4];
        float sum = 0.0f, sq = 0.0f;
        #pragma unroll
        for (int k = 0; k < 4; k++) {
            v[k] = *(const float4*)(x + src + (k * 32 + lane) * 4);
            sum += v[k].x + v[k].y + v[k].z + v[k].w;
            sq  += v[k].x*v[k].x + v[k].y*v[k].y + v[k].z*v[k].z + v[k].w*v[k].w;
        }
        warp_reduce2(sum, sq);
        float mu = sum * (1.0f/512.0f);
        float rstd = rsqrtf(sq * (1.0f/512.0f) - mu*mu + 1e-5f);

        size_t dst = (size_t)r * 512;
        #pragma unroll
        for (int k = 0; k < 4; k++) {
            __half2 h0 = __floats2half2_rn((v[k].x - mu)*rstd*gv[k].x + bv[k].x,
                                           (v[k].y - mu)*rstd*gv[k].y + bv[k].y);
            __half2 h1 = __floats2half2_rn((v[k].z - mu)*rstd*gv[k].z + bv[k].z,
                                           (v[k].w - mu)*rstd*gv[k].w + bv[k].w);
            uint2 u; u.x = *(uint32_t*)&h0; u.y = *(uint32_t*)&h1;
            *(uint2*)(out + dst + (k * 32 + lane) * 4) = u;
        }
    }
    gdc_launch();
    gdc_wait();     // ensure wprep complete before this grid completes
}

// ---------------------------------------------------------------------------
// K5b: LN2 over fp32 hidden (token domain) -> zln fp16.  Warp-per-row.
// ---------------------------------------------------------------------------
__global__ __launch_bounds__(256) void ln2_warp(const float* __restrict__ hid,
                                                const float* __restrict__ g,
                                                const float* __restrict__ b,
                                                __half* __restrict__ zln) {
    gdc_wait();
    int wg = (blockIdx.x * 256 + threadIdx.x) >> 5;
    int lane = threadIdx.x & 31;

    float4 gv[4], bv[4];
    #pragma unroll
    for (int k = 0; k < 4; k++) {
        gv[k] = *(const float4*)(g + (k * 32 + lane) * 4);
        bv[k] = *(const float4*)(b + (k * 32 + lane) * 4);
    }

    #pragma unroll
    for (int rw = 0; rw < 8; rw++) {
        int m = wg * 8 + rw;
        size_t src = (size_t)m * 512;
        float4 v[4];
        float sum = 0.0f, sq = 0.0f;
        #pragma unroll
        for (int k = 0; k < 4; k++) {
            v[k] = *(const float4*)(hid + src + (k * 32 + lane) * 4);
            sum += v[k].x + v[k].y + v[k].z + v[k].w;
            sq  += v[k].x*v[k].x + v[k].y*v[k].y + v[k].z*v[k].z + v[k].w*v[k].w;
        }
        warp_reduce2(sum, sq);
        float mu = sum * (1.0f/512.0f);
        float rstd = rsqrtf(sq * (1.0f/512.0f) - mu*mu + 1e-5f);

        #pragma unroll
        for (int k = 0; k < 4; k++) {
            __half2 h0 = __floats2half2_rn((v[k].x - mu)*rstd*gv[k].x + bv[k].x,
                                           (v[k].y - mu)*rstd*gv[k].y + bv[k].y);
            __half2 h1 = __floats2half2_rn((v[k].z - mu)*rstd*gv[k].z + bv[k].z,
                                           (v[k].w - mu)*rstd*gv[k].w + bv[k].w);
            uint2 u; u.x = *(uint32_t*)&h0; u.y = *(uint32_t*)&h1;
            *(uint2*)(zln + src + (k * 32 + lane) * 4) = u;
        }
    }
    gdc_launch();
}

// ---------------------------------------------------------------------------
// K3: HMMA attention. CTA = (n, head-pair): 256 threads, 8 warps.
// ---------------------------------------------------------------------------
__device__ __forceinline__ int region_id(int c) { return c < 56 ? 0 : (c < 60 ? 1 : 2); }

#define ATT_PITCH 80
#define ATT_TILE  (64 * ATT_PITCH)

__global__ __launch_bounds__(256, 5) void attn_kernel(const __half* __restrict__ qkv,
                                                      __half* __restrict__ ctx) {
    __shared__ __half sAll[2][3][64 * 40];
    __shared__ int val[64];

    gdc_wait();
    const int n = blockIdx.x, t = threadIdx.x;
    const int lane = t & 31, wid = t >> 5;
    const int hg = wid >> 2, w = wid & 3;
    const int h = blockIdx.y * 2 + hg;
    const uint32_t sbase = smem_u32(&sAll[0][0][0]);

    #pragma unroll
    for (int i = 0; i < 6; i++) {
        int f = t + i * 256;
        int hg2  = f / 768;
        int rem  = f - hg2 * 768;
        int part = rem >> 8;
        int rr   = rem & 255;
        int row  = rr >> 2, seg = rr & 3;
        const __half* src = qkv + (size_t)(row * 2048 + n) * 1536
                          + (blockIdx.y * 2 + hg2) * 96 + part * 32 + seg * 8;
        cp16(sbase + (hg2 * 3 + part) * ATT_TILE + row * ATT_PITCH + seg * 16, src);
    }
    CP_COMMIT();
    if (t < 64) {
        int mw = n & 63;
        int hh = ((mw >> 3) << 3) + (t >> 3);
        int ww = ((mw & 7) << 3) + (t & 7);
        val[t] = region_id(hh) * 3 + region_id(ww);
    }
    cp_wait<0>();
    __syncthreads();

    const uint32_t qb = sbase + (hg * 3 + 0) * ATT_TILE;
    const uint32_t kb = sbase + (hg * 3 + 1) * ATT_TILE;
    const uint32_t vb = sbase + (hg * 3 + 2) * ATT_TILE;

    float d[8][4];
    #pragma unroll
    for (int nt = 0; nt < 8; nt++)
        #pragma unroll
        for (int j = 0; j < 4; j++) d[nt][j] = 0.0f;

    #pragma unroll
    for (int ks = 0; ks < 2; ks++) {
        uint32_t af[4];
        ldsm4(af, qb + (w * 16 + (lane & 15)) * ATT_PITCH + (ks * 2 + (lane >> 4)) * 16);
        uint32_t bf[8][2];
        int g = lane >> 3;
        #pragma unroll
        for (int np = 0; np < 4; np++) {
            uint32_t tmp[4];
            ldsm4(tmp, kb + (np * 16 + (g >> 1) * 8 + (lane & 7)) * ATT_PITCH
                          + (ks * 2 + (g & 1)) * 16);
            bf[np*2][0]   = tmp[0]; bf[np*2][1]   = tmp[1];
            bf[np*2+1][0] = tmp[2]; bf[np*2+1][1] = tmp[3];
        }
        #pragma unroll
        for (int nt = 0; nt < 8; nt++) mma16816(d[nt], af, bf[nt]);
    }

    const int r0 = lane >> 2;
    const int c0 = 2 * (lane & 3);
    const int vs0 = val[w * 16 + r0];
    const int vs1 = val[w * 16 + r0 + 8];
    const float SCALE = 0.17677669529663687f;

    float mx0 = -1e30f, mx1 = -1e30f;
    #pragma unroll
    for (int nt = 0; nt < 8; nt++) {
        int vc0 = val[nt * 8 + c0], vc1 = val[nt * 8 + c0 + 1];
        d[nt][0] = (vc0 != vs0) ? -10000.0f : d[nt][0] * SCALE;
        d[nt][1] = (vc1 != vs0) ? -10000.0f : d[nt][1] * SCALE;
        d[nt][2] = (vc0 != vs1) ? -10000.0f : d[nt][2] * SCALE;
        d[nt][3] = (vc1 != vs1) ? -10000.0f : d[nt][3] * SCALE;
        mx0 = fmaxf(mx0, fmaxf(d[nt][0], d[nt][1]));
        mx1 = fmaxf(mx1, fmaxf(d[nt][2], d[nt][3]));
    }
    mx0 = fmaxf(mx0, __shfl_xor_sync(0xffffffffu, mx0, 1));
    mx0 = fmaxf(mx0, __shfl_xor_sync(0xffffffffu, mx0, 2));
    mx1 = fmaxf(mx1, __shfl_xor_sync(0xffffffffu, mx1, 1));
    mx1 = fmaxf(mx1, __shfl_xor_sync(0xffffffffu, mx1, 2));

    float s0 = 0.0f, s1 = 0.0f;
    #pragma unroll
    for (int nt = 0; nt < 8; nt++) {
        d[nt][0] = __expf(d[nt][0] - mx0);
        d[nt][1] = __expf(d[nt][1] - mx0);
        d[nt][2] = __expf(d[nt][2] - mx1);
        d[nt][3] = __expf(d[nt][3] - mx1);
        s0 += d[nt][0] + d[nt][1];
        s1 += d[nt][2] + d[nt][3];
    }
    s0 += __shfl_xor_sync(0xffffffffu, s0, 1);
    s0 += __shfl_xor_sync(0xffffffffu, s0, 2);
    s1 += __shfl_xor_sync(0xffffffffu, s1, 1);
    s1 += __shfl_xor_sync(0xffffffffu, s1, 2);
    const float inv0 = 1.0f / s0, inv1 = 1.0f / s1;

    uint32_t pf[4][4];
    #pragma unroll
    for (int kt = 0; kt < 4; kt++) {
        __half2 a0 = __floats2half2_rn(d[2*kt][0]   * inv0, d[2*kt][1]   * inv0);
        __half2 a1 = __floats2half2_rn(d[2*kt][2]   * inv1, d[2*kt][3]   * inv1);
        __half2 a2 = __floats2half2_rn(d[2*kt+1][0] * inv0, d[2*kt+1][1] * inv0);
        __half2 a3 = __floats2half2_rn(d[2*kt+1][2] * inv1, d[2*kt+1][3] * inv1);
        pf[kt][0] = *(uint32_t*)&a0; pf[kt][1] = *(uint32_t*)&a1;
        pf[kt][2] = *(uint32_t*)&a2; pf[kt][3] = *(uint32_t*)&a3;
    }

    float o[4][4];
    #pragma unroll
    for (int dt = 0; dt < 4; dt++)
        #pragma unroll
        for (int j = 0; j < 4; j++) o[dt][j] = 0.0f;

    {
        int g = lane >> 3;
        #pragma unroll
        for (int kt = 0; kt < 4; kt++) {
            uint32_t bv[4][2];
            #pragma unroll
            for (int dp = 0; dp < 2; dp++) {
                uint32_t tmp[4];
                ldsm4t(tmp, vb + (kt * 16 + (g & 1) * 8 + (lane & 7)) * ATT_PITCH
                               + dp * 32 + (g >> 1) * 16);
                bv[dp*2][0]   = tmp[0]; bv[dp*2][1]   = tmp[1];
                bv[dp*2+1][0] = tmp[2]; bv[dp*2+1][1] = tmp[3];
            }
            #pragma unroll
            for (int dt = 0; dt < 4; dt++) mma16816(o[dt], pf[kt], bv[dt]);
        }
    }
    gdc_launch();

    const int srow0 = w * 16 + r0;
    const size_t base0 = (size_t)(srow0 * 2048 + n) * 512 + h * 32;
    const size_t base1 = (size_t)((srow0 + 8) * 2048 + n) * 512 + h * 32;
    #pragma unroll
    for (int dt = 0; dt < 4; dt++) {
        int c = dt * 8 + c0;
        __half2 h0 = __floats2half2_rn(o[dt][0], o[dt][1]);
        __half2 h1 = __floats2half2_rn(o[dt][2], o[dt][3]);
        *(__half2*)(ctx + base0 + c) = h0;
        *(__half2*)(ctx + base1 + c) = h1;
    }
}

// ---------------------------------------------------------------------------
// hgemm: out[M,Ntot] = A[M,K](fp16) @ Wt[Ntot,K](fp16)^T + bias (+epilogue)
// BM=BN=128, BK=64, 3 stages, 8 warps (2m x 4n), warp tile 64x32.
// Weight (B) prefetch of stages 0-1 issued BEFORE griddepcontrol.wait —
// weights were produced >=2 kernels back, guaranteed complete by PDL induction.
// EPI: 0 fp16 out; 2 gelu -> fp16; 3 fp32 out + rh(zln) + r32(hidden);
//      4 hidden-writer: out32[perm(row)] = acc + bias + rh[row](xw)
//                                          + r32[perm(row)](shortcut)
// ---------------------------------------------------------------------------
#define APITCH   144
#define TILE_B   (128 * APITCH)          // 18432
#define STAGE_B  (2 * TILE_B)            // 36864
#define NSTAGE   3
#define SMEM_T   (NSTAGE * STAGE_B)      // 110592

__device__ __forceinline__ void load_A(uint32_t sm, int stage, const __half* A,
                                       int K, int m0, int kk, int t) {
    uint32_t ab = sm + stage * STAGE_B;
    #pragma unroll
    for (int i = 0; i < 4; i++) {
        int f = t + i * 256;
        int row = f >> 3, seg = f & 7;
        cp16(ab + row * APITCH + seg * 16, A + (size_t)(m0 + row) * K + kk + seg * 8);
    }
    CP_COMMIT();
}
__device__ __forceinline__ void load_Bw(uint32_t sm, int stage, const __half* Bt,
                                        int K, int n0, int kk, int t) {
    uint32_t bb = sm + stage * STAGE_B + TILE_B;
    #pragma unroll
    for (int i = 0; i < 4; i++) {
        int f = t + i * 256;
        int row = f >> 3, seg = f & 7;
        cp16(bb + row * APITCH + seg * 16, Bt + (size_t)(n0 + row) * K + kk + seg * 8);
    }
    CP_COMMIT();
}
__device__ __forceinline__ void load_stage(uint32_t sm, int stage,
                                           const __half* A, const __half* Bt,
                                           int K, int m0, int n0, int kk, int t) {
    uint32_t ab = sm + stage * STAGE_B;
    uint32_t bb = ab + TILE_B;
    #pragma unroll
    for (int i = 0; i < 4; i++) {
        int f = t + i * 256;
        int row = f >> 3, seg = f & 7;
        cp16(ab + row * APITCH + seg * 16, A + (size_t)(m0 + row) * K + kk + seg * 8);
    }
    #pragma unroll
    for (int i = 0; i < 4; i++) {
        int f = t + i * 256;
        int row = f >> 3, seg = f & 7;
        cp16(bb + row * APITCH + seg * 16, Bt + (size_t)(n0 + row) * K + kk + seg * 8);
    }
    CP_COMMIT();
}

__device__ __forceinline__ int perm_row(int R) {
    int s = R >> 11, n = R & 2047;
    int hn = s >> 3, wn = s & 7;
    int i = n >> 8, j = (n >> 5) & 7, b = n & 31;
    int h = ((hn << 3) + i + 4) & 63;
    int w = ((wn << 3) + j + 4) & 63;
    return ((h << 6) + w) * 32 + b;
}

template<int EPI>
__global__ void __launch_bounds__(256) hgemm(
    const __half* __restrict__ A, const __half* __restrict__ Bt,
    const float* __restrict__ bias,
    const float* __restrict__ r32, const __half* __restrict__ rh,
    float* __restrict__ out32, __half* __restrict__ outh,
    int Ntot, int K)
{
    extern __shared__ char smem[];
    uint32_t sm = smem_u32(smem);
    int t = threadIdx.x;
    int lane = t & 31, wid = t >> 5;
    int wm = wid & 1, wn = wid >> 1;
    int m0 = blockIdx.y * 128;
    int n0 = blockIdx.x * 128;
    int NI = K / 64;

    float d[4][4][4];
    #pragma unroll
    for (int a = 0; a < 4; a++)
        #pragma unroll
        for (int b = 0; b < 4; b++)
            #pragma unroll
            for (int c = 0; c < 4; c++) d[a][b][c] = 0.0f;

    // weight prefetch (independent of immediate predecessor), then wait,
    // then the dependent A-tiles.
    load_Bw(sm, 0, Bt, K, n0, 0, t);
    load_Bw(sm, 1, Bt, K, n0, 64, t);
    gdc_wait();
    load_A(sm, 0, A, K, m0, 0, t);
    load_A(sm, 1, A, K, m0, 64, t);

    int st = 0;
    for (int it = 0; it < NI; it++) {
        cp_wait<1>();
        __syncthreads();
        int st2 = st + 2 >= 3 ? st - 1 : st + 2;
        if (it + 2 < NI) load_stage(sm, st2, A, Bt, K, m0, n0, (it + 2) * 64, t);
        else CP_COMMIT();

        uint32_t ab = sm + st * STAGE_B;
        uint32_t bb = ab + TILE_B;
        #pragma unroll
        for (int ks = 0; ks < 4; ks++) {
            uint32_t af[4][4], bf[4][2];
            #pragma unroll
            for (int mt = 0; mt < 4; mt++) {
                int row = wm * 64 + mt * 16 + (lane & 15);
                int seg = ks * 2 + (lane >> 4);
                ldsm4(af[mt], ab + row * APITCH + seg * 16);
            }
            {
                int g = lane >> 3;
                #pragma unroll
                for (int np = 0; np < 2; np++) {
                    uint32_t tmp[4];
                    int row = wn * 32 + np * 16 + (g >> 1) * 8 + (lane & 7);
                    int seg = ks * 2 + (g & 1);
                    ldsm4(tmp, bb + row * APITCH + seg * 16);
                    bf[np*2][0]   = tmp[0]; bf[np*2][1]   = tmp[1];
                    bf[np*2+1][0] = tmp[2]; bf[np*2+1][1] = tmp[3];
                }
            }
            #pragma unroll
            for (int mt = 0; mt < 4; mt++)
                #pragma unroll
                for (int nt = 0; nt < 4; nt++)
                    mma16816(d[mt][nt], af[mt], bf[nt]);
        }
        st = st + 1 >= 3 ? 0 : st + 1;
    }
    gdc_launch();

    // ---------------- epilogue ----------------
    #pragma unroll
    for (int mt = 0; mt < 4; mt++) {
        int r0 = m0 + wm * 64 + mt * 16 + (lane >> 2);
        #pragma unroll
        for (int hf = 0; hf < 2; hf++) {
            int R = r0 + hf * 8;
            size_t gr = (size_t)R * Ntot;
            size_t pr = (EPI == 4) ? (size_t)perm_row(R) * Ntot : 0;
            #pragma unroll
            for (int nt = 0; nt < 4; nt++) {
                int c = n0 + wn * 32 + nt * 8 + (lane & 3) * 2;
                float2 bv = *(const float2*)(bias + c);
                float x = d[mt][nt][hf * 2 + 0] + bv.x;
                float y = d[mt][nt][hf * 2 + 1] + bv.y;
                if (EPI == 0) {
                    *(__half2*)(outh + gr + c) = __floats2half2_rn(x, y);
                } else if (EPI == 2) {
                    *(__half2*)(outh + gr + c) = __floats2half2_rn(gelu_exact(x), gelu_exact(y));
                } else if (EPI == 3) {
                    float2 rv = __half22float2(*(const __half2*)(rh + gr + c));
                    float2 hv = *(const float2*)(r32 + gr + c);
                    float2 o = {x + rv.x + hv.x, y + rv.y + hv.y};
                    *(float2*)(out32 + gr + c) = o;
                } else {  // EPI == 4
                    float2 rv = __half22float2(*(const __half2*)(rh + gr + c));
                    float2 sv = *(const float2*)(r32 + pr + c);
                    float2 o = {x + rv.x + sv.x, y + rv.y + sv.y};
                    *(float2*)(out32 + pr + c) = o;
                }
            }
        }
    }
}

// ---------------------------------------------------------------------------
// Launch (PDL attr on every kernel after the first)
// ---------------------------------------------------------------------------
extern "C" void kernel_launch(void* const* d_in, const int* in_sizes, int n_in,
                              void* d_out, int out_size) {
    const float* hs    = (const float*)d_in[0];
    const float* ln1g  = (const float*)d_in[1];
    const float* ln1b  = (const float*)d_in[2];
    const float* wqkv  = (const float*)d_in[3];
    const float* bqkv  = (const float*)d_in[4];
    const float* wproj = (const float*)d_in[5];
    const float* bproj = (const float*)d_in[6];
    const float* ln2g  = (const float*)d_in[7];
    const float* ln2b  = (const float*)d_in[8];
    const float* wfc1  = (const float*)d_in[9];
    const float* bfc1  = (const float*)d_in[10];
    const float* wfc2  = (const float*)d_in[11];
    const float* bfc2  = (const float*)d_in[12];
    float* out = (float*)d_out;

    __half *p_xw, *p_qkv, *p_ctx, *p_zln, *p_fc1, *p_wq, *p_wp, *p_w1, *p_w2;
    float *p_hid;
    cudaGetSymbolAddress((void**)&p_xw,  g_xw);
    cudaGetSymbolAddress((void**)&p_qkv, g_qkv);
    cudaGetSymbolAddress((void**)&p_ctx, g_ctx);
    cudaGetSymbolAddress((void**)&p_hid, g_hid);
    cudaGetSymbolAddress((void**)&p_zln, g_zln);
    cudaGetSymbolAddress((void**)&p_fc1, g_fc1);
    cudaGetSymbolAddress((void**)&p_wq,  g_wq);
    cudaGetSymbolAddress((void**)&p_wp,  g_wp);
    cudaGetSymbolAddress((void**)&p_w1,  g_w1);
    cudaGetSymbolAddress((void**)&p_w2,  g_w2);

    cudaFuncSetAttribute(hgemm<0>, cudaFuncAttributeMaxDynamicSharedMemorySize, SMEM_T);
    cudaFuncSetAttribute(hgemm<2>, cudaFuncAttributeMaxDynamicSharedMemorySize, SMEM_T);
    cudaFuncSetAttribute(hgemm<3>, cudaFuncAttributeMaxDynamicSharedMemorySize, SMEM_T);
    cudaFuncSetAttribute(hgemm<4>, cudaFuncAttributeMaxDynamicSharedMemorySize, SMEM_T);

    cudaLaunchAttribute pdl[1];
    pdl[0].id = cudaLaunchAttributeProgrammaticStreamSerialization;
    pdl[0].val.programmaticStreamSerializationAllowed = 1;

    // K0: fused weight transpose (no PDL attr; chain head)
    wprep_all<<<3072, 256>>>(wqkv, wproj, wfc1, wfc2, p_wq, p_wp, p_w1, p_w2);

    cudaLaunchConfig_t cfg{};
    cfg.stream = 0;
    cfg.attrs = pdl;
    cfg.numAttrs = 1;

    // K1: LN1 + shift + partition
    cfg.gridDim = dim3(2048); cfg.blockDim = dim3(256); cfg.dynamicSmemBytes = 0;
    cudaLaunchKernelEx(&cfg, ln_shift_warp, hs, ln1g, ln1b, (__half*)p_xw);

    // K2: qkv = xw @ Wqkv + b  -> fp16
    cfg.gridDim = dim3(12, 1024); cfg.dynamicSmemBytes = SMEM_T;
    cudaLaunchKernelEx(&cfg, hgemm<0>, (const __half*)p_xw, (const __half*)p_wq, bqkv,
                       (const float*)nullptr, (const __half*)nullptr,
                       (float*)nullptr, (__half*)p_qkv, 1536, 512);

    // K3: attention
    cfg.gridDim = dim3(2048, 8); cfg.dynamicSmemBytes = 0;
    cudaLaunchKernelEx(&cfg, attn_kernel, (const __half*)p_qkv, (__half*)p_ctx);

    // K4: hidden[perm] = ctx @ Wproj + b + xw + shortcut[perm]
    cfg.gridDim = dim3(4, 1024); cfg.dynamicSmemBytes = SMEM_T;
    cudaLaunchKernelEx(&cfg, hgemm<4>, (const __half*)p_ctx, (const __half*)p_wp, bproj,
                       (const float*)hs, (const __half*)p_xw,
                       (float*)p_hid, (__half*)nullptr, 512, 512);

    // K5: zln = LN2(hidden)
    cfg.gridDim = dim3(2048); cfg.dynamicSmemBytes = 0;
    cudaLaunchKernelEx(&cfg, ln2_warp, (const float*)p_hid, ln2g, ln2b, (__half*)p_zln);

    // K6: fc1 = gelu(zln @ Wfc1 + b) -> fp16
    cfg.gridDim = dim3(16, 1024); cfg.dynamicSmemBytes = SMEM_T;
    cudaLaunchKernelEx(&cfg, hgemm<2>, (const __half*)p_zln, (const __half*)p_w1, bfc1,
                       (const float*)nullptr, (const __half*)nullptr,
                       (float*)nullptr, (__half*)p_fc1, 2048, 512);

    // K7: out = fc1 @ Wfc2 + b + zln + hidden
    cfg.gridDim = dim3(4, 1024); cfg.dynamicSmemBytes = SMEM_T;
    cudaLaunchKernelEx(&cfg, hgemm<3>, (const __half*)p_fc1, (const __half*)p_w2, bfc2,
                       (const float*)p_hid, (const __half*)p_zln,
                       (float*)out, (__half*)nullptr, 512, 2048);
}